// round 11
// baseline (speedup 1.0000x reference)
#include <cuda_runtime.h>
#include <cuda_fp16.h>

#define NB 32
#define NN 100000
#define NE 1000000
#define NH 64
#define NL 3
#define NRELP 231
#define NTA 365
#define NENT 7128
#define FULLM 0xffffffffu
#define CH 1024
#define NCHUNK 98   // ceil(NN/CH)

typedef unsigned long long ull;

// ---------------- device scratch ----------------
static __device__ float   g_next[NN * NH];                       // 25.6 MB (pre-relu aggregate)
static __device__ __align__(16) __half2 g_hWh[3 * NN * 32];      // 38.4 MB transformed hidden (fp16)
static __device__ __align__(16) __half2 g_RWh[3 * NRELP * 32];   // rela @ W_cls^T (fp16)
static __device__ __align__(16) __half2 g_TWh[3 * NTA * 32];     // time @ W_cls^T (fp16, layer-invariant)
static __device__ int2    g_eMeta[NE];              // {src|cls<<17|ta<<19, dst|rel<<17|b<<25}
static __device__ float   g_score[NE];
static __device__ float   g_hv[NN * 8];
static __device__ float   g_rq[NB * NRELP * 8];
static __device__ int     g_hist[NN];
static __device__ int     g_off[NN];

#define FMA2(d, a, b, c) \
    asm("fma.rn.f32x2 %0, %1, %2, %3;" : "=l"(d) : "l"(a), "l"(b), "l"(c))

__device__ __forceinline__ ull dup_f(float x) {
    ull r; unsigned u = __float_as_uint(x);
    asm("mov.b64 %0, {%1, %1};" : "=l"(r) : "r"(u));
    return r;
}
__device__ __forceinline__ void red4(float* p, float x, float y, float z, float w) {
    asm volatile("red.global.add.v4.f32 [%0], {%1, %2, %3, %4};"
                 :: "l"(p), "f"(x), "f"(y), "f"(z), "f"(w) : "memory");
}

// ---------------- fused init: g_next, g_hist, out ----------------
__global__ void init_kernel(float* out, int n_out) {
    int i = blockIdx.x * blockDim.x + threadIdx.x;
    int stride = gridDim.x * blockDim.x;
    const int n4 = NN * NH / 4;
    for (int j = i; j < n4; j += stride)
        ((float4*)g_next)[j] = make_float4(0.f, 0.f, 0.f, 0.f);
    for (int j = i; j < NN; j += stride) g_hist[j] = 0;
    for (int j = i; j < n_out; j += stride) out[j] = 0.f;
}

// ---------------- zero g_next (between layers, after hw consumed it) ----------------
__global__ void zero_next_kernel() {
    int i = blockIdx.x * blockDim.x + threadIdx.x;
    const int n4 = NN * NH / 4;
    if (i < n4) ((float4*)g_next)[i] = make_float4(0.f, 0.f, 0.f, 0.f);
}

// ---------------- counting sort by src ----------------
__global__ void hist_kernel(const int* __restrict__ src_idx) {
    int e = blockIdx.x * blockDim.x + threadIdx.x;
    if (e < NE) atomicAdd(&g_hist[src_idx[e]], 1);
}
__global__ void offscan_kernel() {
    __shared__ int sd[256];
    __shared__ int sbase;
    int b = blockIdx.x, t = threadIdx.x;
    int lim = b * CH;
    int s = 0;
    for (int i = t; i < lim; i += 256) s += g_hist[i];
    sd[t] = s; __syncthreads();
    for (int o = 128; o; o >>= 1) { if (t < o) sd[t] += sd[t + o]; __syncthreads(); }
    if (t == 0) sbase = sd[0];
    __syncthreads();
    int chunkbase = sbase;
    __syncthreads();
    int idx = b * CH + t * 4;
    int h0 = (idx + 0 < NN) ? g_hist[idx + 0] : 0;
    int h1 = (idx + 1 < NN) ? g_hist[idx + 1] : 0;
    int h2 = (idx + 2 < NN) ? g_hist[idx + 2] : 0;
    int h3 = (idx + 3 < NN) ? g_hist[idx + 3] : 0;
    int sum = h0 + h1 + h2 + h3;
    sd[t] = sum; __syncthreads();
    for (int o = 1; o < 256; o <<= 1) {
        int v = (t >= o) ? sd[t - o] : 0;
        __syncthreads();
        sd[t] += v;
        __syncthreads();
    }
    int base = chunkbase + sd[t] - sum;
    if (idx + 0 < NN) g_off[idx + 0] = base;
    if (idx + 1 < NN) g_off[idx + 1] = base + h0;
    if (idx + 2 < NN) g_off[idx + 2] = base + h0 + h1;
    if (idx + 3 < NN) g_off[idx + 3] = base + h0 + h1 + h2;
}
__global__ void scatter_sort_kernel(const int* __restrict__ src_idx,
                                    const int* __restrict__ dst_idx,
                                    const int* __restrict__ rel_idx,
                                    const int* __restrict__ rel_time,
                                    const int* __restrict__ batch_idx) {
    int e = blockIdx.x * blockDim.x + threadIdx.x;
    if (e >= NE) return;
    int src = src_idx[e];
    int rt  = rel_time[e];
    int cls = rt > 0 ? 2 : (rt == 0 ? 1 : 0);  // 0=past(Wp) 1=now(Wn) 2=future(Wf)
    int ta  = rt < 0 ? -rt : rt;
    int rel = rel_idx[e];
    int pos = atomicAdd(&g_off[src], 1);
    g_eMeta[pos] = make_int2(src | (cls << 17) | (ta << 19),
                             dst_idx[e] | (rel << 17) | (batch_idx[e] << 25));
}

// ---------------- per-layer tables (fp16 out) ----------------
__global__ void rwtw_kernel(const float* __restrict__ relaL,
                            const float* __restrict__ timeE,
                            const float* __restrict__ Wp,
                            const float* __restrict__ Wn,
                            const float* __restrict__ Wf) {
    int w = (blockIdx.x * blockDim.x + threadIdx.x) >> 5;
    int lane = threadIdx.x & 31;
    const int NROW = 3 * NRELP + 3 * NTA;   // 1788
    if (w >= NROW) return;
    const float* in; __half2* out; int cls;
    if (w < 3 * NRELP) {
        cls = w / NRELP;
        in = relaL + (w % NRELP) * NH;
        out = g_RWh + w * 32;
    } else {
        int w2 = w - 3 * NRELP;
        cls = w2 / NTA;
        in = timeE + (w2 % NTA) * NH;
        out = g_TWh + w2 * 32;
    }
    const float* W = (cls == 0) ? Wp : ((cls == 1) ? Wn : Wf);
    float2 ev = __ldg((const float2*)&in[2 * lane]);
    int h0 = 2 * lane;
    float a0 = 0.f, a1 = 0.f;
#pragma unroll 8
    for (int k2 = 0; k2 < 32; ++k2) {
        float bx = __shfl_sync(FULLM, ev.x, k2);
        float by = __shfl_sync(FULLM, ev.y, k2);
        float2 w0 = __ldg((const float2*)&W[h0 * 64 + 2 * k2]);
        float2 w1 = __ldg((const float2*)&W[(h0 + 1) * 64 + 2 * k2]);
        a0 += bx * w0.x + by * w0.y;
        a1 += bx * w1.x + by * w1.y;
    }
    out[lane] = __floats2half2_rn(a0, a1);
}

// rq[b*231+r][a] = rela[r].W1seg1_a + rela[qr_b].W1seg2_a
__global__ void rq_kernel(const float* __restrict__ relaL,
                          const float* __restrict__ W1L,
                          const int* __restrict__ query_rel) {
    int w = (blockIdx.x * blockDim.x + threadIdx.x) >> 5;
    int lane = threadIdx.x & 31;
    if (w >= NB * NRELP) return;
    int b = w / NRELP, r = w % NRELP;
    int qrb = __ldg(&query_rel[b]);
    float2 re = __ldg((const float2*)&relaL[r * 64 + 2 * lane]);
    float2 qe = __ldg((const float2*)&relaL[qrb * 64 + 2 * lane]);
    float p[5];
#pragma unroll
    for (int a = 0; a < 5; ++a) {
        float2 v  = __ldg((const float2*)&W1L[a * 192 + 64 + 2 * lane]);
        float2 ww = __ldg((const float2*)&W1L[a * 192 + 128 + 2 * lane]);
        p[a] = re.x * v.x + re.y * v.y + qe.x * ww.x + qe.y * ww.y;
    }
#pragma unroll
    for (int a = 0; a < 5; ++a)
#pragma unroll
        for (int off = 16; off; off >>= 1) p[a] += __shfl_xor_sync(FULLM, p[a], off);
    if (lane == 0) {
#pragma unroll
        for (int a = 0; a < 5; ++a) g_rq[w * 8 + a] = p[a];
    }
}

// hW[cls][node] = relu(g_next)[node] @ W_cls^T -> fp16; cls==0 blocks also emit hv
__global__ void __launch_bounds__(256) hw_kernel(const float* __restrict__ Wp,
                                                 const float* __restrict__ Wn,
                                                 const float* __restrict__ Wf,
                                                 const float* __restrict__ W1L) {
    extern __shared__ float dyn[];
    float* sW = dyn;            // 4352 floats
    float* sT = dyn + 4352;     // 128*66 floats
    float* sU = dyn + 4352 + 128 * 66;  // 5*64 floats
    int cls = blockIdx.y;
    const float* W = (cls == 0) ? Wp : ((cls == 1) ? Wn : Wf);
    int t = threadIdx.x;
    for (int idx = t; idx < 4096; idx += 256) {
        int h = idx >> 6, k = idx & 63;
        sW[k * 68 + h + (h >= 32 ? 4 : 0)] = __ldg(&W[h * 64 + k]);
    }
    if (cls == 0) {
        for (int idx = t; idx < 5 * 64; idx += 256) {
            int a = idx >> 6, k = idx & 63;
            sU[idx] = __ldg(&W1L[a * 192 + k]);
        }
    }
    __syncthreads();
    for (int tile = blockIdx.x * 128; tile < NN; tile += gridDim.x * 128) {
        int nN = min(128, NN - tile);
        for (int j = t; j < nN * 32; j += 256) {
            int nl = j >> 5, l = j & 31;
            float2 v = *(const float2*)&g_next[(size_t)(tile + nl) * 64 + 2 * l];
            v.x = fmaxf(v.x, 0.f); v.y = fmaxf(v.y, 0.f);   // relu inline
            *(float2*)&sT[nl * 66 + 2 * l] = v;
        }
        __syncthreads();
        int slot = t >> 1, p = t & 1;
        if (slot < nN) {
            // hv (cls 0 only): pair half-dots + shfl combine
            if (cls == 0) {
                const float* row = sT + slot * 66 + p * 32;
                float pa[5] = {0.f, 0.f, 0.f, 0.f, 0.f};
#pragma unroll 8
                for (int k = 0; k < 32; ++k) {
                    float hk = row[k];
#pragma unroll
                    for (int a = 0; a < 5; ++a) pa[a] += hk * sU[a * 64 + p * 32 + k];
                }
#pragma unroll
                for (int a = 0; a < 5; ++a) pa[a] += __shfl_xor_sync(FULLM, pa[a], 1);
                if (p == 0) {
                    float* hvp = g_hv + (size_t)(tile + slot) * 8;
                    *(float4*)hvp = make_float4(pa[0], pa[1], pa[2], pa[3]);
                    hvp[4] = pa[4];
                }
            }
            const float* wb = sW + p * 36;
            const float* er = sT + slot * 66;
            ull acc[16];
#pragma unroll
            for (int j = 0; j < 16; ++j) acc[j] = 0ull;
#pragma unroll 4
            for (int k2 = 0; k2 < 32; ++k2) {
                float2 e2 = *(const float2*)&er[2 * k2];
                ull b0 = dup_f(e2.x);
                ull b1 = dup_f(e2.y);
                const float* r0 = wb + (2 * k2) * 68;
                const float* r1 = r0 + 68;
#pragma unroll
                for (int j = 0; j < 8; ++j) {
                    ulonglong2 w0 = *(const ulonglong2*)(r0 + 4 * j);
                    FMA2(acc[2 * j],     w0.x, b0, acc[2 * j]);
                    FMA2(acc[2 * j + 1], w0.y, b0, acc[2 * j + 1]);
                }
#pragma unroll
                for (int j = 0; j < 8; ++j) {
                    ulonglong2 w1 = *(const ulonglong2*)(r1 + 4 * j);
                    FMA2(acc[2 * j],     w1.x, b1, acc[2 * j]);
                    FMA2(acc[2 * j + 1], w1.y, b1, acc[2 * j + 1]);
                }
            }
            __half2 hh[16];
#pragma unroll
            for (int j = 0; j < 16; ++j) {
                float2 f = *(float2*)&acc[j];
                hh[j] = __float22half2_rn(f);
            }
            __half2* ob = g_hWh + ((size_t)cls * NN + tile + slot) * 32 + p * 16;
#pragma unroll
            for (int j = 0; j < 4; ++j)
                *(uint4*)(ob + 4 * j) = *(uint4*)(hh + 4 * j);
        }
        __syncthreads();
    }
}

// ---------------- per-edge score ----------------
__global__ void score_kernel(const float* __restrict__ W2L, int isL0) {
    int e = blockIdx.x * blockDim.x + threadIdx.x;
    if (e >= NE) return;
    int2 m = __ldg(&g_eMeta[e]);
    int src = m.x & 0x1FFFF;
    int rel = (m.y >> 17) & 0xFF;
    int b   = (m.y >> 25) & 0x1F;
    const float4* rq4 = (const float4*)&g_rq[(b * NRELP + rel) * 8];
    float4 r0 = __ldg(&rq4[0]); float4 r1 = __ldg(&rq4[1]);
    float p0 = r0.x, p1 = r0.y, p2 = r0.z, p3 = r0.w, p4 = r1.x;
    if (!isL0) {
        const float4* hv4 = (const float4*)&g_hv[src * 8];
        float4 h0 = __ldg(&hv4[0]); float4 h1 = __ldg(&hv4[1]);
        p0 += h0.x; p1 += h0.y; p2 += h0.z; p3 += h0.w; p4 += h1.x;
    }
    float z = fmaxf(p0, 0.f) * __ldg(&W2L[0]) + fmaxf(p1, 0.f) * __ldg(&W2L[1])
            + fmaxf(p2, 0.f) * __ldg(&W2L[2]) + fmaxf(p3, 0.f) * __ldg(&W2L[3])
            + fmaxf(p4, 0.f) * __ldg(&W2L[4]);
    g_score[e] = 1.f / (1.f + __expf(-z));
}

// ---------------- main edge kernel (quarter-warp per edge, fp16 tables) ----------------
// lanes grouped 8-wide: group q owns edge base+4p+q; lane ql owns dims [8ql, 8ql+8)
__global__ void __launch_bounds__(256) edge_kernel(int isL0) {
    int gw = (blockIdx.x * blockDim.x + threadIdx.x) >> 5;
    int lane = threadIdx.x & 31;
    int q  = lane >> 3;
    int ql = lane & 7;
    int nw = (gridDim.x * blockDim.x) >> 5;
    for (int base = gw * 8; base < NE; base += nw * 8) {
#pragma unroll
        for (int p = 0; p < 2; ++p) {
            int e = base + 4 * p + q;
            int2 m = __ldg(&g_eMeta[e]);
            float s = __ldg(&g_score[e]);
            int src = m.x & 0x1FFFF;
            int cls = (m.x >> 17) & 3;
            int ta  = (m.x >> 19) & 0x1FF;
            int dst = m.y & 0x1FFFF;
            int rel = (m.y >> 17) & 0xFF;
            uint4 ra = __ldg((const uint4*)(g_RWh + (cls * NRELP + rel) * 32 + 4 * ql));
            uint4 tb = __ldg((const uint4*)(g_TWh + (cls * NTA + ta) * 32 + 4 * ql));
            __half2 t0 = __hadd2(*(__half2*)&ra.x, *(__half2*)&tb.x);
            __half2 t1 = __hadd2(*(__half2*)&ra.y, *(__half2*)&tb.y);
            __half2 t2 = __hadd2(*(__half2*)&ra.z, *(__half2*)&tb.z);
            __half2 t3 = __hadd2(*(__half2*)&ra.w, *(__half2*)&tb.w);
            if (!isL0) {
                uint4 hw = __ldg((const uint4*)(g_hWh + ((size_t)cls * NN + src) * 32 + 4 * ql));
                t0 = __hadd2(t0, *(__half2*)&hw.x);
                t1 = __hadd2(t1, *(__half2*)&hw.y);
                t2 = __hadd2(t2, *(__half2*)&hw.z);
                t3 = __hadd2(t3, *(__half2*)&hw.w);
            }
            float2 f0 = __half22float2(t0), f1 = __half22float2(t1);
            float2 f2 = __half22float2(t2), f3 = __half22float2(t3);
            float* ob = &g_next[(size_t)dst * 64 + 8 * ql];
            red4(ob,     s * f0.x, s * f0.y, s * f1.x, s * f1.y);
            red4(ob + 4, s * f2.x, s * f2.y, s * f3.x, s * f3.y);
        }
    }
}

// ---------------- output: relu(g_next).Wc + bc ----------------
__global__ void out_kernel(const float* __restrict__ Wc, const float* __restrict__ bc,
                           const int* __restrict__ ob, const int* __restrict__ oe,
                           float* __restrict__ out) {
    int gw = (blockIdx.x * blockDim.x + threadIdx.x) >> 5;
    int lane = threadIdx.x & 31;
    if (gw >= NN) return;
    float2 h = *(const float2*)&g_next[(size_t)gw * 64 + 2 * lane];
    h.x = fmaxf(h.x, 0.f); h.y = fmaxf(h.y, 0.f);
    float2 w = __ldg((const float2*)&Wc[2 * lane]);
    float p = h.x * w.x + h.y * w.y;
#pragma unroll
    for (int off = 16; off; off >>= 1) p += __shfl_xor_sync(FULLM, p, off);
    if (lane == 0) out[ob[gw] * NENT + oe[gw]] = p + bc[0];
}

// ---------------- host launch ----------------
extern "C" void kernel_launch(void* const* d_in, const int* in_sizes, int n_in,
                              void* d_out, int out_size) {
    const int *bt, *si, *di, *ri, *rt, *qr, *ob, *oe;
    const float *rela, *te, *Wp, *Wn, *Wf, *W1, *W2, *Wc, *bc;

    if (in_sizes[0] == NE) {
        bt = (const int*)d_in[0];  si = (const int*)d_in[1];
        di = (const int*)d_in[2];  ri = (const int*)d_in[3];
        rt = (const int*)d_in[4];  qr = (const int*)d_in[5];
        ob = (const int*)d_in[6];  oe = (const int*)d_in[7];
        rela = (const float*)d_in[8];  te = (const float*)d_in[9];
        Wp = (const float*)d_in[10]; Wn = (const float*)d_in[11];
        Wf = (const float*)d_in[12]; W1 = (const float*)d_in[13];
        W2 = (const float*)d_in[14]; Wc = (const float*)d_in[15];
        bc = (const float*)d_in[16];
    } else {
        rela = (const float*)d_in[0];  te = (const float*)d_in[1];
        Wp = (const float*)d_in[2]; Wn = (const float*)d_in[3];
        Wf = (const float*)d_in[4]; W1 = (const float*)d_in[5];
        W2 = (const float*)d_in[6]; Wc = (const float*)d_in[7];
        bc = (const float*)d_in[8];
        bt = (const int*)d_in[9];  si = (const int*)d_in[10];
        di = (const int*)d_in[11]; ri = (const int*)d_in[12];
        rt = (const int*)d_in[13]; qr = (const int*)d_in[14];
        ob = (const int*)d_in[15]; oe = (const int*)d_in[16];
    }

    float* out = (float*)d_out;

    static int attr_done = 0;
    const int hw_smem = (4352 + 128 * 66 + 5 * 64) * 4;   // 52480 B
    if (!attr_done) {
        cudaFuncSetAttribute(hw_kernel, cudaFuncAttributeMaxDynamicSharedMemorySize, hw_smem);
        attr_done = 1;
    }

    const int n4 = NN * NH / 4;

    init_kernel<<<1600, 256>>>(out, out_size);

    // counting sort by src
    hist_kernel<<<(NE + 255) / 256, 256>>>(si);
    offscan_kernel<<<NCHUNK, 256>>>();
    scatter_sort_kernel<<<(NE + 255) / 256, 256>>>(si, di, ri, rt, bt);

    for (int layer = 0; layer < NL; ++layer) {
        const float* relaL = rela + layer * NRELP * NH;
        const float* W1L = W1 + layer * 5 * 192;
        int isL0 = (layer == 0) ? 1 : 0;
        int tblrows = isL0 ? 1788 : 693;   // TW layer-invariant
        rwtw_kernel<<<(tblrows * 32 + 255) / 256, 256>>>(relaL, te, Wp, Wn, Wf);
        rq_kernel<<<(NB * NRELP * 32 + 255) / 256, 256>>>(relaL, W1L, qr);
        if (!isL0) {
            // hW + hv from relu(g_next) of previous layer, then clear accumulator
            hw_kernel<<<dim3((NN + 127) / 128, 3), 256, hw_smem>>>(Wp, Wn, Wf, W1L);
            zero_next_kernel<<<(n4 + 255) / 256, 256>>>();
        }
        score_kernel<<<(NE + 255) / 256, 256>>>(W2 + layer * 5, isL0);
        edge_kernel<<<1184, 256>>>(isL0);
    }

    out_kernel<<<(NN * 32 + 255) / 256, 256>>>(Wc, bc, ob, oe, out);
}

// round 12
// speedup vs baseline: 1.1827x; 1.1827x over previous
#include <cuda_runtime.h>
#include <cuda_fp16.h>

#define NB 32
#define NN 100000
#define NE 1000000
#define NH 64
#define NL 3
#define NRELP 231
#define NTA 365
#define NENT 7128
#define FULLM 0xffffffffu
#define CH 1024
#define NCHUNK 98   // ceil(NN/CH)

typedef unsigned long long ull;

// ---------------- device scratch ----------------
static __device__ float   g_next[NN * NH];                       // 25.6 MB (pre-relu aggregate)
static __device__ __align__(16) __half2 g_hWh[3 * NN * 32];      // 38.4 MB transformed hidden (fp16)
static __device__ __align__(16) __half2 g_RWh[3 * NRELP * 32];   // rela @ W_cls^T (fp16)
static __device__ __align__(16) __half2 g_TWh[3 * NTA * 32];     // time @ W_cls^T (fp16, layer-invariant)
static __device__ int2    g_eMeta[NE];              // {src|cls<<17|ta<<19, dst|rel<<17|b<<25}
static __device__ float   g_score[NE];
static __device__ float   g_hv[NN * 8];
static __device__ float   g_rq[NB * NRELP * 8];
static __device__ int     g_hist[NN];
static __device__ int     g_off[NN];

#define FMA2(d, a, b, c) \
    asm("fma.rn.f32x2 %0, %1, %2, %3;" : "=l"(d) : "l"(a), "l"(b), "l"(c))

__device__ __forceinline__ ull dup_f(float x) {
    ull r; unsigned u = __float_as_uint(x);
    asm("mov.b64 %0, {%1, %1};" : "=l"(r) : "r"(u));
    return r;
}
__device__ __forceinline__ void red4(float* p, float x, float y, float z, float w) {
    asm volatile("red.global.add.v4.f32 [%0], {%1, %2, %3, %4};"
                 :: "l"(p), "f"(x), "f"(y), "f"(z), "f"(w) : "memory");
}

// ---------------- fused init: g_next, g_hist, out ----------------
__global__ void init_kernel(float* out, int n_out) {
    int i = blockIdx.x * blockDim.x + threadIdx.x;
    int stride = gridDim.x * blockDim.x;
    const int n4 = NN * NH / 4;
    for (int j = i; j < n4; j += stride)
        ((float4*)g_next)[j] = make_float4(0.f, 0.f, 0.f, 0.f);
    for (int j = i; j < NN; j += stride) g_hist[j] = 0;
    for (int j = i; j < n_out; j += stride) out[j] = 0.f;
}

// ---------------- zero g_next (between layers, after hw consumed it) ----------------
__global__ void zero_next_kernel() {
    int i = blockIdx.x * blockDim.x + threadIdx.x;
    const int n4 = NN * NH / 4;
    if (i < n4) ((float4*)g_next)[i] = make_float4(0.f, 0.f, 0.f, 0.f);
}

// ---------------- counting sort by src ----------------
__global__ void hist_kernel(const int* __restrict__ src_idx) {
    int e = blockIdx.x * blockDim.x + threadIdx.x;
    if (e < NE) atomicAdd(&g_hist[src_idx[e]], 1);
}
__global__ void offscan_kernel() {
    __shared__ int sd[256];
    __shared__ int sbase;
    int b = blockIdx.x, t = threadIdx.x;
    int lim = b * CH;
    int s = 0;
    for (int i = t; i < lim; i += 256) s += g_hist[i];
    sd[t] = s; __syncthreads();
    for (int o = 128; o; o >>= 1) { if (t < o) sd[t] += sd[t + o]; __syncthreads(); }
    if (t == 0) sbase = sd[0];
    __syncthreads();
    int chunkbase = sbase;
    __syncthreads();
    int idx = b * CH + t * 4;
    int h0 = (idx + 0 < NN) ? g_hist[idx + 0] : 0;
    int h1 = (idx + 1 < NN) ? g_hist[idx + 1] : 0;
    int h2 = (idx + 2 < NN) ? g_hist[idx + 2] : 0;
    int h3 = (idx + 3 < NN) ? g_hist[idx + 3] : 0;
    int sum = h0 + h1 + h2 + h3;
    sd[t] = sum; __syncthreads();
    for (int o = 1; o < 256; o <<= 1) {
        int v = (t >= o) ? sd[t - o] : 0;
        __syncthreads();
        sd[t] += v;
        __syncthreads();
    }
    int base = chunkbase + sd[t] - sum;
    if (idx + 0 < NN) g_off[idx + 0] = base;
    if (idx + 1 < NN) g_off[idx + 1] = base + h0;
    if (idx + 2 < NN) g_off[idx + 2] = base + h0 + h1;
    if (idx + 3 < NN) g_off[idx + 3] = base + h0 + h1 + h2;
}
__global__ void scatter_sort_kernel(const int* __restrict__ src_idx,
                                    const int* __restrict__ dst_idx,
                                    const int* __restrict__ rel_idx,
                                    const int* __restrict__ rel_time,
                                    const int* __restrict__ batch_idx) {
    int e = blockIdx.x * blockDim.x + threadIdx.x;
    if (e >= NE) return;
    int src = src_idx[e];
    int rt  = rel_time[e];
    int cls = rt > 0 ? 2 : (rt == 0 ? 1 : 0);  // 0=past(Wp) 1=now(Wn) 2=future(Wf)
    int ta  = rt < 0 ? -rt : rt;
    int rel = rel_idx[e];
    int pos = atomicAdd(&g_off[src], 1);
    g_eMeta[pos] = make_int2(src | (cls << 17) | (ta << 19),
                             dst_idx[e] | (rel << 17) | (batch_idx[e] << 25));
}

// ---------------- per-layer tables (fp16 out) ----------------
__global__ void rwtw_kernel(const float* __restrict__ relaL,
                            const float* __restrict__ timeE,
                            const float* __restrict__ Wp,
                            const float* __restrict__ Wn,
                            const float* __restrict__ Wf) {
    int w = (blockIdx.x * blockDim.x + threadIdx.x) >> 5;
    int lane = threadIdx.x & 31;
    const int NROW = 3 * NRELP + 3 * NTA;   // 1788
    if (w >= NROW) return;
    const float* in; __half2* out; int cls;
    if (w < 3 * NRELP) {
        cls = w / NRELP;
        in = relaL + (w % NRELP) * NH;
        out = g_RWh + w * 32;
    } else {
        int w2 = w - 3 * NRELP;
        cls = w2 / NTA;
        in = timeE + (w2 % NTA) * NH;
        out = g_TWh + w2 * 32;
    }
    const float* W = (cls == 0) ? Wp : ((cls == 1) ? Wn : Wf);
    float2 ev = __ldg((const float2*)&in[2 * lane]);
    int h0 = 2 * lane;
    float a0 = 0.f, a1 = 0.f;
#pragma unroll 8
    for (int k2 = 0; k2 < 32; ++k2) {
        float bx = __shfl_sync(FULLM, ev.x, k2);
        float by = __shfl_sync(FULLM, ev.y, k2);
        float2 w0 = __ldg((const float2*)&W[h0 * 64 + 2 * k2]);
        float2 w1 = __ldg((const float2*)&W[(h0 + 1) * 64 + 2 * k2]);
        a0 += bx * w0.x + by * w0.y;
        a1 += bx * w1.x + by * w1.y;
    }
    out[lane] = __floats2half2_rn(a0, a1);
}

// rq[b*231+r][a] = rela[r].W1seg1_a + rela[qr_b].W1seg2_a
__global__ void rq_kernel(const float* __restrict__ relaL,
                          const float* __restrict__ W1L,
                          const int* __restrict__ query_rel) {
    int w = (blockIdx.x * blockDim.x + threadIdx.x) >> 5;
    int lane = threadIdx.x & 31;
    if (w >= NB * NRELP) return;
    int b = w / NRELP, r = w % NRELP;
    int qrb = __ldg(&query_rel[b]);
    float2 re = __ldg((const float2*)&relaL[r * 64 + 2 * lane]);
    float2 qe = __ldg((const float2*)&relaL[qrb * 64 + 2 * lane]);
    float p[5];
#pragma unroll
    for (int a = 0; a < 5; ++a) {
        float2 v  = __ldg((const float2*)&W1L[a * 192 + 64 + 2 * lane]);
        float2 ww = __ldg((const float2*)&W1L[a * 192 + 128 + 2 * lane]);
        p[a] = re.x * v.x + re.y * v.y + qe.x * ww.x + qe.y * ww.y;
    }
#pragma unroll
    for (int a = 0; a < 5; ++a)
#pragma unroll
        for (int off = 16; off; off >>= 1) p[a] += __shfl_xor_sync(FULLM, p[a], off);
    if (lane == 0) {
#pragma unroll
        for (int a = 0; a < 5; ++a) g_rq[w * 8 + a] = p[a];
    }
}

// hW[cls][node] = relu(g_next)[node] @ W_cls^T -> fp16; cls==0 blocks also emit hv
__global__ void __launch_bounds__(256) hw_kernel(const float* __restrict__ Wp,
                                                 const float* __restrict__ Wn,
                                                 const float* __restrict__ Wf,
                                                 const float* __restrict__ W1L) {
    extern __shared__ float dyn[];
    float* sW = dyn;            // 4352 floats
    float* sT = dyn + 4352;     // 128*66 floats
    float* sU = dyn + 4352 + 128 * 66;  // 5*64 floats
    int cls = blockIdx.y;
    const float* W = (cls == 0) ? Wp : ((cls == 1) ? Wn : Wf);
    int t = threadIdx.x;
    for (int idx = t; idx < 4096; idx += 256) {
        int h = idx >> 6, k = idx & 63;
        sW[k * 68 + h + (h >= 32 ? 4 : 0)] = __ldg(&W[h * 64 + k]);
    }
    if (cls == 0) {
        for (int idx = t; idx < 5 * 64; idx += 256) {
            int a = idx >> 6, k = idx & 63;
            sU[idx] = __ldg(&W1L[a * 192 + k]);
        }
    }
    __syncthreads();
    for (int tile = blockIdx.x * 128; tile < NN; tile += gridDim.x * 128) {
        int nN = min(128, NN - tile);
        for (int j = t; j < nN * 32; j += 256) {
            int nl = j >> 5, l = j & 31;
            float2 v = *(const float2*)&g_next[(size_t)(tile + nl) * 64 + 2 * l];
            v.x = fmaxf(v.x, 0.f); v.y = fmaxf(v.y, 0.f);   // relu inline
            *(float2*)&sT[nl * 66 + 2 * l] = v;
        }
        __syncthreads();
        int slot = t >> 1, p = t & 1;
        if (slot < nN) {
            // hv (cls 0 only): pair half-dots + shfl combine
            if (cls == 0) {
                const float* row = sT + slot * 66 + p * 32;
                float pa[5] = {0.f, 0.f, 0.f, 0.f, 0.f};
#pragma unroll 8
                for (int k = 0; k < 32; ++k) {
                    float hk = row[k];
#pragma unroll
                    for (int a = 0; a < 5; ++a) pa[a] += hk * sU[a * 64 + p * 32 + k];
                }
#pragma unroll
                for (int a = 0; a < 5; ++a) pa[a] += __shfl_xor_sync(FULLM, pa[a], 1);
                if (p == 0) {
                    float* hvp = g_hv + (size_t)(tile + slot) * 8;
                    *(float4*)hvp = make_float4(pa[0], pa[1], pa[2], pa[3]);
                    hvp[4] = pa[4];
                }
            }
            const float* wb = sW + p * 36;
            const float* er = sT + slot * 66;
            ull acc[16];
#pragma unroll
            for (int j = 0; j < 16; ++j) acc[j] = 0ull;
#pragma unroll 4
            for (int k2 = 0; k2 < 32; ++k2) {
                float2 e2 = *(const float2*)&er[2 * k2];
                ull b0 = dup_f(e2.x);
                ull b1 = dup_f(e2.y);
                const float* r0 = wb + (2 * k2) * 68;
                const float* r1 = r0 + 68;
#pragma unroll
                for (int j = 0; j < 8; ++j) {
                    ulonglong2 w0 = *(const ulonglong2*)(r0 + 4 * j);
                    FMA2(acc[2 * j],     w0.x, b0, acc[2 * j]);
                    FMA2(acc[2 * j + 1], w0.y, b0, acc[2 * j + 1]);
                }
#pragma unroll
                for (int j = 0; j < 8; ++j) {
                    ulonglong2 w1 = *(const ulonglong2*)(r1 + 4 * j);
                    FMA2(acc[2 * j],     w1.x, b1, acc[2 * j]);
                    FMA2(acc[2 * j + 1], w1.y, b1, acc[2 * j + 1]);
                }
            }
            __half2 hh[16];
#pragma unroll
            for (int j = 0; j < 16; ++j) {
                float2 f = *(float2*)&acc[j];
                hh[j] = __float22half2_rn(f);
            }
            __half2* ob = g_hWh + ((size_t)cls * NN + tile + slot) * 32 + p * 16;
#pragma unroll
            for (int j = 0; j < 4; ++j)
                *(uint4*)(ob + 4 * j) = *(uint4*)(hh + 4 * j);
        }
        __syncthreads();
    }
}

// ---------------- per-edge score ----------------
__global__ void score_kernel(const float* __restrict__ W2L, int isL0) {
    int e = blockIdx.x * blockDim.x + threadIdx.x;
    if (e >= NE) return;
    int2 m = __ldg(&g_eMeta[e]);
    int src = m.x & 0x1FFFF;
    int rel = (m.y >> 17) & 0xFF;
    int b   = (m.y >> 25) & 0x1F;
    const float4* rq4 = (const float4*)&g_rq[(b * NRELP + rel) * 8];
    float4 r0 = __ldg(&rq4[0]); float4 r1 = __ldg(&rq4[1]);
    float p0 = r0.x, p1 = r0.y, p2 = r0.z, p3 = r0.w, p4 = r1.x;
    if (!isL0) {
        const float4* hv4 = (const float4*)&g_hv[src * 8];
        float4 h0 = __ldg(&hv4[0]); float4 h1 = __ldg(&hv4[1]);
        p0 += h0.x; p1 += h0.y; p2 += h0.z; p3 += h0.w; p4 += h1.x;
    }
    float z = fmaxf(p0, 0.f) * __ldg(&W2L[0]) + fmaxf(p1, 0.f) * __ldg(&W2L[1])
            + fmaxf(p2, 0.f) * __ldg(&W2L[2]) + fmaxf(p3, 0.f) * __ldg(&W2L[3])
            + fmaxf(p4, 0.f) * __ldg(&W2L[4]);
    g_score[e] = 1.f / (1.f + __expf(-z));
}

// ---------------- main edge kernel (half-warp per edge, fp16 tables) ----------------
// lanes 0-15 own edge e (dims 4*hl..4*hl+3), lanes 16-31 edge e+1 (R10 geometry).
__global__ void __launch_bounds__(256) edge_kernel(int isL0) {
    int gw = (blockIdx.x * blockDim.x + threadIdx.x) >> 5;
    int lane = threadIdx.x & 31;
    int half = lane >> 4;
    int hl = lane & 15;
    int nw = (gridDim.x * blockDim.x) >> 5;
    for (int base = gw * 8; base < NE; base += nw * 8) {
#pragma unroll
        for (int p = 0; p < 4; ++p) {
            int e = base + 2 * p + half;
            int2 m = __ldg(&g_eMeta[e]);
            float s = __ldg(&g_score[e]);
            int src = m.x & 0x1FFFF;
            int cls = (m.x >> 17) & 3;
            int ta  = (m.x >> 19) & 0x1FF;
            int dst = m.y & 0x1FFFF;
            int rel = (m.y >> 17) & 0xFF;
            uint2 ra = __ldg((const uint2*)(g_RWh + (cls * NRELP + rel) * 32 + 2 * hl));
            uint2 tb = __ldg((const uint2*)(g_TWh + (cls * NTA + ta) * 32 + 2 * hl));
            __half2 t0 = __hadd2(*(__half2*)&ra.x, *(__half2*)&tb.x);
            __half2 t1 = __hadd2(*(__half2*)&ra.y, *(__half2*)&tb.y);
            if (!isL0) {
                uint2 hw = __ldg((const uint2*)(g_hWh + ((size_t)cls * NN + src) * 32 + 2 * hl));
                t0 = __hadd2(t0, *(__half2*)&hw.x);
                t1 = __hadd2(t1, *(__half2*)&hw.y);
            }
            float2 f01 = __half22float2(t0);
            float2 f23 = __half22float2(t1);
            red4(&g_next[(size_t)dst * 64 + 4 * hl], s * f01.x, s * f01.y, s * f23.x, s * f23.y);
        }
    }
}

// ---------------- output: relu(g_next).Wc + bc ----------------
__global__ void out_kernel(const float* __restrict__ Wc, const float* __restrict__ bc,
                           const int* __restrict__ ob, const int* __restrict__ oe,
                           float* __restrict__ out) {
    int gw = (blockIdx.x * blockDim.x + threadIdx.x) >> 5;
    int lane = threadIdx.x & 31;
    if (gw >= NN) return;
    float2 h = *(const float2*)&g_next[(size_t)gw * 64 + 2 * lane];
    h.x = fmaxf(h.x, 0.f); h.y = fmaxf(h.y, 0.f);
    float2 w = __ldg((const float2*)&Wc[2 * lane]);
    float p = h.x * w.x + h.y * w.y;
#pragma unroll
    for (int off = 16; off; off >>= 1) p += __shfl_xor_sync(FULLM, p, off);
    if (lane == 0) out[ob[gw] * NENT + oe[gw]] = p + bc[0];
}

// ---------------- host launch ----------------
extern "C" void kernel_launch(void* const* d_in, const int* in_sizes, int n_in,
                              void* d_out, int out_size) {
    const int *bt, *si, *di, *ri, *rt, *qr, *ob, *oe;
    const float *rela, *te, *Wp, *Wn, *Wf, *W1, *W2, *Wc, *bc;

    if (in_sizes[0] == NE) {
        bt = (const int*)d_in[0];  si = (const int*)d_in[1];
        di = (const int*)d_in[2];  ri = (const int*)d_in[3];
        rt = (const int*)d_in[4];  qr = (const int*)d_in[5];
        ob = (const int*)d_in[6];  oe = (const int*)d_in[7];
        rela = (const float*)d_in[8];  te = (const float*)d_in[9];
        Wp = (const float*)d_in[10]; Wn = (const float*)d_in[11];
        Wf = (const float*)d_in[12]; W1 = (const float*)d_in[13];
        W2 = (const float*)d_in[14]; Wc = (const float*)d_in[15];
        bc = (const float*)d_in[16];
    } else {
        rela = (const float*)d_in[0];  te = (const float*)d_in[1];
        Wp = (const float*)d_in[2]; Wn = (const float*)d_in[3];
        Wf = (const float*)d_in[4]; W1 = (const float*)d_in[5];
        W2 = (const float*)d_in[6]; Wc = (const float*)d_in[7];
        bc = (const float*)d_in[8];
        bt = (const int*)d_in[9];  si = (const int*)d_in[10];
        di = (const int*)d_in[11]; ri = (const int*)d_in[12];
        rt = (const int*)d_in[13]; qr = (const int*)d_in[14];
        ob = (const int*)d_in[15]; oe = (const int*)d_in[16];
    }

    float* out = (float*)d_out;

    static int attr_done = 0;
    const int hw_smem = (4352 + 128 * 66 + 5 * 64) * 4;   // 52480 B
    if (!attr_done) {
        cudaFuncSetAttribute(hw_kernel, cudaFuncAttributeMaxDynamicSharedMemorySize, hw_smem);
        attr_done = 1;
    }

    const int n4 = NN * NH / 4;

    init_kernel<<<1600, 256>>>(out, out_size);

    // counting sort by src
    hist_kernel<<<(NE + 255) / 256, 256>>>(si);
    offscan_kernel<<<NCHUNK, 256>>>();
    scatter_sort_kernel<<<(NE + 255) / 256, 256>>>(si, di, ri, rt, bt);

    for (int layer = 0; layer < NL; ++layer) {
        const float* relaL = rela + layer * NRELP * NH;
        const float* W1L = W1 + layer * 5 * 192;
        int isL0 = (layer == 0) ? 1 : 0;
        int tblrows = isL0 ? 1788 : 693;   // TW layer-invariant
        rwtw_kernel<<<(tblrows * 32 + 255) / 256, 256>>>(relaL, te, Wp, Wn, Wf);
        rq_kernel<<<(NB * NRELP * 32 + 255) / 256, 256>>>(relaL, W1L, qr);
        if (!isL0) {
            // hW + hv from relu(g_next) of previous layer, then clear accumulator
            hw_kernel<<<dim3((NN + 127) / 128, 3), 256, hw_smem>>>(Wp, Wn, Wf, W1L);
            zero_next_kernel<<<(n4 + 255) / 256, 256>>>();
        }
        score_kernel<<<(NE + 255) / 256, 256>>>(W2 + layer * 5, isL0);
        edge_kernel<<<1184, 256>>>(isL0);
    }

    out_kernel<<<(NN * 32 + 255) / 256, 256>>>(Wc, bc, ob, oe, out);
}

// round 13
// speedup vs baseline: 1.2226x; 1.0338x over previous
#include <cuda_runtime.h>
#include <cuda_fp16.h>

#define NB 32
#define NN 100000
#define NE 1000000
#define NH 64
#define NL 3
#define NRELP 231
#define NTA 365
#define NENT 7128
#define FULLM 0xffffffffu
#define CH 1024
#define NCHUNK 98   // ceil(NN/CH)

typedef unsigned long long ull;

// ---------------- device scratch ----------------
static __device__ float   g_next[NN * NH];                       // 25.6 MB (pre-relu aggregate)
static __device__ __align__(16) __half2 g_hWh[3 * NN * 32];      // 38.4 MB transformed hidden (fp16)
static __device__ __align__(16) __half2 g_RWh[3 * NRELP * 32];   // rela @ W_cls^T (fp16)
static __device__ __align__(16) __half2 g_TWh[3 * NTA * 32];     // time @ W_cls^T (fp16, layer-invariant)
static __device__ __align__(16) int2 g_eMeta[NE];   // {src|cls<<17|ta<<19, dst|rel<<17|b<<25}
static __device__ __align__(8) float g_score[NE];
static __device__ float   g_score0[NB * NRELP];     // layer-0 score table (hidden=0)
static __device__ float   g_hv[NN * 8];
static __device__ float   g_rq[NB * NRELP * 8];
static __device__ int     g_hist[NN];
static __device__ int     g_off[NN];

#define FMA2(d, a, b, c) \
    asm("fma.rn.f32x2 %0, %1, %2, %3;" : "=l"(d) : "l"(a), "l"(b), "l"(c))

__device__ __forceinline__ ull dup_f(float x) {
    ull r; unsigned u = __float_as_uint(x);
    asm("mov.b64 %0, {%1, %1};" : "=l"(r) : "r"(u));
    return r;
}
__device__ __forceinline__ void red4(float* p, float x, float y, float z, float w) {
    asm volatile("red.global.add.v4.f32 [%0], {%1, %2, %3, %4};"
                 :: "l"(p), "f"(x), "f"(y), "f"(z), "f"(w) : "memory");
}

// ---------------- fused init: g_next, g_hist, out ----------------
__global__ void init_kernel(float* out, int n_out) {
    int i = blockIdx.x * blockDim.x + threadIdx.x;
    int stride = gridDim.x * blockDim.x;
    const int n4 = NN * NH / 4;
    for (int j = i; j < n4; j += stride)
        ((float4*)g_next)[j] = make_float4(0.f, 0.f, 0.f, 0.f);
    for (int j = i; j < NN; j += stride) g_hist[j] = 0;
    for (int j = i; j < n_out; j += stride) out[j] = 0.f;
}

// ---------------- zero g_next (between layers, after hw consumed it) ----------------
__global__ void zero_next_kernel() {
    int i = blockIdx.x * blockDim.x + threadIdx.x;
    const int n4 = NN * NH / 4;
    if (i < n4) ((float4*)g_next)[i] = make_float4(0.f, 0.f, 0.f, 0.f);
}

// ---------------- counting sort by src ----------------
__global__ void hist_kernel(const int* __restrict__ src_idx) {
    int e = blockIdx.x * blockDim.x + threadIdx.x;
    if (e < NE) atomicAdd(&g_hist[src_idx[e]], 1);
}
__global__ void offscan_kernel() {
    __shared__ int sd[256];
    __shared__ int sbase;
    int b = blockIdx.x, t = threadIdx.x;
    int lim = b * CH;
    int s = 0;
    for (int i = t; i < lim; i += 256) s += g_hist[i];
    sd[t] = s; __syncthreads();
    for (int o = 128; o; o >>= 1) { if (t < o) sd[t] += sd[t + o]; __syncthreads(); }
    if (t == 0) sbase = sd[0];
    __syncthreads();
    int chunkbase = sbase;
    __syncthreads();
    int idx = b * CH + t * 4;
    int h0 = (idx + 0 < NN) ? g_hist[idx + 0] : 0;
    int h1 = (idx + 1 < NN) ? g_hist[idx + 1] : 0;
    int h2 = (idx + 2 < NN) ? g_hist[idx + 2] : 0;
    int h3 = (idx + 3 < NN) ? g_hist[idx + 3] : 0;
    int sum = h0 + h1 + h2 + h3;
    sd[t] = sum; __syncthreads();
    for (int o = 1; o < 256; o <<= 1) {
        int v = (t >= o) ? sd[t - o] : 0;
        __syncthreads();
        sd[t] += v;
        __syncthreads();
    }
    int base = chunkbase + sd[t] - sum;
    if (idx + 0 < NN) g_off[idx + 0] = base;
    if (idx + 1 < NN) g_off[idx + 1] = base + h0;
    if (idx + 2 < NN) g_off[idx + 2] = base + h0 + h1;
    if (idx + 3 < NN) g_off[idx + 3] = base + h0 + h1 + h2;
}
__global__ void scatter_sort_kernel(const int* __restrict__ src_idx,
                                    const int* __restrict__ dst_idx,
                                    const int* __restrict__ rel_idx,
                                    const int* __restrict__ rel_time,
                                    const int* __restrict__ batch_idx) {
    int e = blockIdx.x * blockDim.x + threadIdx.x;
    if (e >= NE) return;
    int src = src_idx[e];
    int rt  = rel_time[e];
    int cls = rt > 0 ? 2 : (rt == 0 ? 1 : 0);  // 0=past(Wp) 1=now(Wn) 2=future(Wf)
    int ta  = rt < 0 ? -rt : rt;
    int rel = rel_idx[e];
    int pos = atomicAdd(&g_off[src], 1);
    g_eMeta[pos] = make_int2(src | (cls << 17) | (ta << 19),
                             dst_idx[e] | (rel << 17) | (batch_idx[e] << 25));
}

// ---------------- per-layer tables: RW/TW (fp16) + rq + score0, one kernel ----------------
__global__ void tables_kernel(const float* __restrict__ relaL,
                              const float* __restrict__ timeE,
                              const float* __restrict__ Wp,
                              const float* __restrict__ Wn,
                              const float* __restrict__ Wf,
                              const float* __restrict__ W1L,
                              const float* __restrict__ W2L,
                              const int* __restrict__ query_rel,
                              int tblrows) {
    int w = (blockIdx.x * blockDim.x + threadIdx.x) >> 5;
    int lane = threadIdx.x & 31;
    if (w < tblrows) {
        const float* in; __half2* out; int cls;
        if (w < 3 * NRELP) {
            cls = w / NRELP;
            in = relaL + (w % NRELP) * NH;
            out = g_RWh + w * 32;
        } else {
            int w2 = w - 3 * NRELP;
            cls = w2 / NTA;
            in = timeE + (w2 % NTA) * NH;
            out = g_TWh + w2 * 32;
        }
        const float* W = (cls == 0) ? Wp : ((cls == 1) ? Wn : Wf);
        float2 ev = __ldg((const float2*)&in[2 * lane]);
        int h0 = 2 * lane;
        float a0 = 0.f, a1 = 0.f;
#pragma unroll 8
        for (int k2 = 0; k2 < 32; ++k2) {
            float bx = __shfl_sync(FULLM, ev.x, k2);
            float by = __shfl_sync(FULLM, ev.y, k2);
            float2 w0 = __ldg((const float2*)&W[h0 * 64 + 2 * k2]);
            float2 w1 = __ldg((const float2*)&W[(h0 + 1) * 64 + 2 * k2]);
            a0 += bx * w0.x + by * w0.y;
            a1 += bx * w1.x + by * w1.y;
        }
        out[lane] = __floats2half2_rn(a0, a1);
        return;
    }
    int wq = w - tblrows;
    if (wq >= NB * NRELP) return;
    int b = wq / NRELP, r = wq % NRELP;
    int qrb = __ldg(&query_rel[b]);
    float2 re = __ldg((const float2*)&relaL[r * 64 + 2 * lane]);
    float2 qe = __ldg((const float2*)&relaL[qrb * 64 + 2 * lane]);
    float p[5];
#pragma unroll
    for (int a = 0; a < 5; ++a) {
        float2 v  = __ldg((const float2*)&W1L[a * 192 + 64 + 2 * lane]);
        float2 ww = __ldg((const float2*)&W1L[a * 192 + 128 + 2 * lane]);
        p[a] = re.x * v.x + re.y * v.y + qe.x * ww.x + qe.y * ww.y;
    }
#pragma unroll
    for (int a = 0; a < 5; ++a)
#pragma unroll
        for (int off = 16; off; off >>= 1) p[a] += __shfl_xor_sync(FULLM, p[a], off);
    if (lane == 0) {
#pragma unroll
        for (int a = 0; a < 5; ++a) g_rq[wq * 8 + a] = p[a];
        // layer-0 score (hidden=0): depends only on (b, rel)
        float z = 0.f;
#pragma unroll
        for (int a = 0; a < 5; ++a) z += fmaxf(p[a], 0.f) * __ldg(&W2L[a]);
        g_score0[wq] = 1.f / (1.f + __expf(-z));
    }
}

// hW[cls][node] = relu(g_next)[node] @ W_cls^T -> fp16; cls==0 blocks also emit hv
__global__ void __launch_bounds__(256) hw_kernel(const float* __restrict__ Wp,
                                                 const float* __restrict__ Wn,
                                                 const float* __restrict__ Wf,
                                                 const float* __restrict__ W1L) {
    extern __shared__ float dyn[];
    float* sW = dyn;            // 4352 floats
    float* sT = dyn + 4352;     // 128*66 floats
    float* sU = dyn + 4352 + 128 * 66;  // 5*64 floats
    int cls = blockIdx.y;
    const float* W = (cls == 0) ? Wp : ((cls == 1) ? Wn : Wf);
    int t = threadIdx.x;
    for (int idx = t; idx < 4096; idx += 256) {
        int h = idx >> 6, k = idx & 63;
        sW[k * 68 + h + (h >= 32 ? 4 : 0)] = __ldg(&W[h * 64 + k]);
    }
    if (cls == 0) {
        for (int idx = t; idx < 5 * 64; idx += 256) {
            int a = idx >> 6, k = idx & 63;
            sU[idx] = __ldg(&W1L[a * 192 + k]);
        }
    }
    __syncthreads();
    for (int tile = blockIdx.x * 128; tile < NN; tile += gridDim.x * 128) {
        int nN = min(128, NN - tile);
        for (int j = t; j < nN * 32; j += 256) {
            int nl = j >> 5, l = j & 31;
            float2 v = *(const float2*)&g_next[(size_t)(tile + nl) * 64 + 2 * l];
            v.x = fmaxf(v.x, 0.f); v.y = fmaxf(v.y, 0.f);   // relu inline
            *(float2*)&sT[nl * 66 + 2 * l] = v;
        }
        __syncthreads();
        int slot = t >> 1, p = t & 1;
        if (slot < nN) {
            if (cls == 0) {
                const float* row = sT + slot * 66 + p * 32;
                float pa[5] = {0.f, 0.f, 0.f, 0.f, 0.f};
#pragma unroll 8
                for (int k = 0; k < 32; ++k) {
                    float hk = row[k];
#pragma unroll
                    for (int a = 0; a < 5; ++a) pa[a] += hk * sU[a * 64 + p * 32 + k];
                }
#pragma unroll
                for (int a = 0; a < 5; ++a) pa[a] += __shfl_xor_sync(FULLM, pa[a], 1);
                if (p == 0) {
                    float* hvp = g_hv + (size_t)(tile + slot) * 8;
                    *(float4*)hvp = make_float4(pa[0], pa[1], pa[2], pa[3]);
                    hvp[4] = pa[4];
                }
            }
            const float* wb = sW + p * 36;
            const float* er = sT + slot * 66;
            ull acc[16];
#pragma unroll
            for (int j = 0; j < 16; ++j) acc[j] = 0ull;
#pragma unroll 4
            for (int k2 = 0; k2 < 32; ++k2) {
                float2 e2 = *(const float2*)&er[2 * k2];
                ull b0 = dup_f(e2.x);
                ull b1 = dup_f(e2.y);
                const float* r0 = wb + (2 * k2) * 68;
                const float* r1 = r0 + 68;
#pragma unroll
                for (int j = 0; j < 8; ++j) {
                    ulonglong2 w0 = *(const ulonglong2*)(r0 + 4 * j);
                    FMA2(acc[2 * j],     w0.x, b0, acc[2 * j]);
                    FMA2(acc[2 * j + 1], w0.y, b0, acc[2 * j + 1]);
                }
#pragma unroll
                for (int j = 0; j < 8; ++j) {
                    ulonglong2 w1 = *(const ulonglong2*)(r1 + 4 * j);
                    FMA2(acc[2 * j],     w1.x, b1, acc[2 * j]);
                    FMA2(acc[2 * j + 1], w1.y, b1, acc[2 * j + 1]);
                }
            }
            __half2 hh[16];
#pragma unroll
            for (int j = 0; j < 16; ++j) {
                float2 f = *(float2*)&acc[j];
                hh[j] = __float22half2_rn(f);
            }
            __half2* ob = g_hWh + ((size_t)cls * NN + tile + slot) * 32 + p * 16;
#pragma unroll
            for (int j = 0; j < 4; ++j)
                *(uint4*)(ob + 4 * j) = *(uint4*)(hh + 4 * j);
        }
        __syncthreads();
    }
}

// ---------------- per-edge score (layers > 0), 2 edges per thread ----------------
__global__ void score_kernel(const float* __restrict__ W2L) {
    int i = blockIdx.x * blockDim.x + threadIdx.x;
    int e0 = 2 * i;
    if (e0 >= NE) return;
    int4 mm = __ldg((const int4*)&g_eMeta[e0]);   // two int2 metas
    float w20 = __ldg(&W2L[0]), w21 = __ldg(&W2L[1]), w22 = __ldg(&W2L[2]);
    float w23 = __ldg(&W2L[3]), w24 = __ldg(&W2L[4]);
    float sc[2];
#pragma unroll
    for (int k = 0; k < 2; ++k) {
        int mx = k ? mm.z : mm.x;
        int my = k ? mm.w : mm.y;
        int src = mx & 0x1FFFF;
        int rel = (my >> 17) & 0xFF;
        int b   = (my >> 25) & 0x1F;
        const float4* rq4 = (const float4*)&g_rq[(b * NRELP + rel) * 8];
        float4 r0 = __ldg(&rq4[0]); float4 r1 = __ldg(&rq4[1]);
        const float4* hv4 = (const float4*)&g_hv[src * 8];
        float4 h0 = __ldg(&hv4[0]); float4 h1 = __ldg(&hv4[1]);
        float z = fmaxf(r0.x + h0.x, 0.f) * w20 + fmaxf(r0.y + h0.y, 0.f) * w21
                + fmaxf(r0.z + h0.z, 0.f) * w22 + fmaxf(r0.w + h0.w, 0.f) * w23
                + fmaxf(r1.x + h1.x, 0.f) * w24;
        sc[k] = 1.f / (1.f + __expf(-z));
    }
    *(float2*)&g_score[e0] = make_float2(sc[0], sc[1]);
}

// ---------------- main edge kernel (half-warp per edge, fp16 tables) ----------------
__global__ void __launch_bounds__(256) edge_kernel(int isL0) {
    int gw = (blockIdx.x * blockDim.x + threadIdx.x) >> 5;
    int lane = threadIdx.x & 31;
    int half = lane >> 4;
    int hl = lane & 15;
    int nw = (gridDim.x * blockDim.x) >> 5;
    for (int base = gw * 8; base < NE; base += nw * 8) {
#pragma unroll
        for (int p = 0; p < 4; ++p) {
            int e = base + 2 * p + half;
            int2 m = __ldg(&g_eMeta[e]);
            int src = m.x & 0x1FFFF;
            int cls = (m.x >> 17) & 3;
            int ta  = (m.x >> 19) & 0x1FF;
            int dst = m.y & 0x1FFFF;
            int rel = (m.y >> 17) & 0xFF;
            float s;
            if (isL0) {
                int b = (m.y >> 25) & 0x1F;
                s = __ldg(&g_score0[b * NRELP + rel]);
            } else {
                s = __ldg(&g_score[e]);
            }
            uint2 ra = __ldg((const uint2*)(g_RWh + (cls * NRELP + rel) * 32 + 2 * hl));
            uint2 tb = __ldg((const uint2*)(g_TWh + (cls * NTA + ta) * 32 + 2 * hl));
            __half2 t0 = __hadd2(*(__half2*)&ra.x, *(__half2*)&tb.x);
            __half2 t1 = __hadd2(*(__half2*)&ra.y, *(__half2*)&tb.y);
            if (!isL0) {
                uint2 hw = __ldg((const uint2*)(g_hWh + ((size_t)cls * NN + src) * 32 + 2 * hl));
                t0 = __hadd2(t0, *(__half2*)&hw.x);
                t1 = __hadd2(t1, *(__half2*)&hw.y);
            }
            float2 f01 = __half22float2(t0);
            float2 f23 = __half22float2(t1);
            red4(&g_next[(size_t)dst * 64 + 4 * hl], s * f01.x, s * f01.y, s * f23.x, s * f23.y);
        }
    }
}

// ---------------- output: relu(g_next).Wc + bc ----------------
__global__ void out_kernel(const float* __restrict__ Wc, const float* __restrict__ bc,
                           const int* __restrict__ ob, const int* __restrict__ oe,
                           float* __restrict__ out) {
    int gw = (blockIdx.x * blockDim.x + threadIdx.x) >> 5;
    int lane = threadIdx.x & 31;
    if (gw >= NN) return;
    float2 h = *(const float2*)&g_next[(size_t)gw * 64 + 2 * lane];
    h.x = fmaxf(h.x, 0.f); h.y = fmaxf(h.y, 0.f);
    float2 w = __ldg((const float2*)&Wc[2 * lane]);
    float p = h.x * w.x + h.y * w.y;
#pragma unroll
    for (int off = 16; off; off >>= 1) p += __shfl_xor_sync(FULLM, p, off);
    if (lane == 0) out[ob[gw] * NENT + oe[gw]] = p + bc[0];
}

// ---------------- host launch ----------------
extern "C" void kernel_launch(void* const* d_in, const int* in_sizes, int n_in,
                              void* d_out, int out_size) {
    const int *bt, *si, *di, *ri, *rt, *qr, *ob, *oe;
    const float *rela, *te, *Wp, *Wn, *Wf, *W1, *W2, *Wc, *bc;

    if (in_sizes[0] == NE) {
        bt = (const int*)d_in[0];  si = (const int*)d_in[1];
        di = (const int*)d_in[2];  ri = (const int*)d_in[3];
        rt = (const int*)d_in[4];  qr = (const int*)d_in[5];
        ob = (const int*)d_in[6];  oe = (const int*)d_in[7];
        rela = (const float*)d_in[8];  te = (const float*)d_in[9];
        Wp = (const float*)d_in[10]; Wn = (const float*)d_in[11];
        Wf = (const float*)d_in[12]; W1 = (const float*)d_in[13];
        W2 = (const float*)d_in[14]; Wc = (const float*)d_in[15];
        bc = (const float*)d_in[16];
    } else {
        rela = (const float*)d_in[0];  te = (const float*)d_in[1];
        Wp = (const float*)d_in[2]; Wn = (const float*)d_in[3];
        Wf = (const float*)d_in[4]; W1 = (const float*)d_in[5];
        W2 = (const float*)d_in[6]; Wc = (const float*)d_in[7];
        bc = (const float*)d_in[8];
        bt = (const int*)d_in[9];  si = (const int*)d_in[10];
        di = (const int*)d_in[11]; ri = (const int*)d_in[12];
        rt = (const int*)d_in[13]; qr = (const int*)d_in[14];
        ob = (const int*)d_in[15]; oe = (const int*)d_in[16];
    }

    float* out = (float*)d_out;

    static int attr_done = 0;
    const int hw_smem = (4352 + 128 * 66 + 5 * 64) * 4;   // 52480 B
    if (!attr_done) {
        cudaFuncSetAttribute(hw_kernel, cudaFuncAttributeMaxDynamicSharedMemorySize, hw_smem);
        attr_done = 1;
    }

    const int n4 = NN * NH / 4;

    init_kernel<<<1600, 256>>>(out, out_size);

    // counting sort by src
    hist_kernel<<<(NE + 255) / 256, 256>>>(si);
    offscan_kernel<<<NCHUNK, 256>>>();
    scatter_sort_kernel<<<(NE + 255) / 256, 256>>>(si, di, ri, rt, bt);

    for (int layer = 0; layer < NL; ++layer) {
        const float* relaL = rela + layer * NRELP * NH;
        const float* W1L = W1 + layer * 5 * 192;
        const float* W2L = W2 + layer * 5;
        int isL0 = (layer == 0) ? 1 : 0;
        int tblrows = isL0 ? 1788 : 693;   // TW layer-invariant
        int tot_warps = tblrows + NB * NRELP;
        tables_kernel<<<(tot_warps * 32 + 255) / 256, 256>>>(
            relaL, te, Wp, Wn, Wf, W1L, W2L, qr, tblrows);
        if (!isL0) {
            hw_kernel<<<dim3((NN + 127) / 128, 3), 256, hw_smem>>>(Wp, Wn, Wf, W1L);
            zero_next_kernel<<<(n4 + 255) / 256, 256>>>();
            score_kernel<<<(NE / 2 + 255) / 256, 256>>>(W2L);
        }
        edge_kernel<<<1184, 256>>>(isL0);
    }

    out_kernel<<<(NN * 32 + 255) / 256, 256>>>(Wc, bc, ob, oe, out);
}

// round 14
// speedup vs baseline: 1.2389x; 1.0133x over previous
#include <cuda_runtime.h>
#include <cuda_fp16.h>

#define NB 32
#define NN 100000
#define NE 1000000
#define NH 64
#define NL 3
#define NRELP 231
#define NTA 365
#define NENT 7128
#define FULLM 0xffffffffu
#define CH 1024
#define NCHUNK 98   // ceil(NN/CH)
#define RWROWS (NL * 3 * NRELP)     // 2079
#define TWROWS (3 * NTA)            // 1095
#define RQROWS (NB * NRELP)         // 7392

typedef unsigned long long ull;

// ---------------- device scratch ----------------
static __device__ float   g_next[NN * NH];                       // 25.6 MB (pre-relu aggregate)
static __device__ __align__(16) __half2 g_hWh[3 * NN * 32];      // 38.4 MB transformed hidden (fp16)
static __device__ __align__(16) __half2 g_RWh[RWROWS * 32];      // [layer][cls][rel] rela @ W^T (fp16)
static __device__ __align__(16) __half2 g_TWh[TWROWS * 32];      // [cls][ta] time @ W^T (fp16)
static __device__ __align__(16) int2 g_eMeta[NE];   // {src|cls<<17|ta<<19, dst|rel<<17|b<<25}
static __device__ __align__(8) float g_score[NE];
static __device__ float   g_score0[RQROWS];         // layer-0 score table (hidden=0)
static __device__ float   g_hv[NN * 8];
static __device__ float   g_rq[NL * RQROWS * 8];    // [layer][b*NRELP+rel][8]
static __device__ int     g_hist[NN];
static __device__ int     g_off[NN];

#define FMA2(d, a, b, c) \
    asm("fma.rn.f32x2 %0, %1, %2, %3;" : "=l"(d) : "l"(a), "l"(b), "l"(c))

__device__ __forceinline__ ull dup_f(float x) {
    ull r; unsigned u = __float_as_uint(x);
    asm("mov.b64 %0, {%1, %1};" : "=l"(r) : "r"(u));
    return r;
}
__device__ __forceinline__ void red4(float* p, float x, float y, float z, float w) {
    asm volatile("red.global.add.v4.f32 [%0], {%1, %2, %3, %4};"
                 :: "l"(p), "f"(x), "f"(y), "f"(z), "f"(w) : "memory");
}

// ---------------- fused init: g_next, g_hist, out ----------------
__global__ void init_kernel(float* out, int n_out) {
    int i = blockIdx.x * blockDim.x + threadIdx.x;
    int stride = gridDim.x * blockDim.x;
    const int n4 = NN * NH / 4;
    for (int j = i; j < n4; j += stride)
        ((float4*)g_next)[j] = make_float4(0.f, 0.f, 0.f, 0.f);
    for (int j = i; j < NN; j += stride) g_hist[j] = 0;
    for (int j = i; j < n_out; j += stride) out[j] = 0.f;
}

// ---------------- zero g_next (between layers, after hw consumed it) ----------------
__global__ void zero_next_kernel() {
    int i = blockIdx.x * blockDim.x + threadIdx.x;
    const int n4 = NN * NH / 4;
    if (i < n4) ((float4*)g_next)[i] = make_float4(0.f, 0.f, 0.f, 0.f);
}

// ---------------- counting sort by src ----------------
__global__ void hist_kernel(const int* __restrict__ src_idx) {
    int e = blockIdx.x * blockDim.x + threadIdx.x;
    if (e < NE) atomicAdd(&g_hist[src_idx[e]], 1);
}
__global__ void offscan_kernel() {
    __shared__ int sd[256];
    __shared__ int sbase;
    int b = blockIdx.x, t = threadIdx.x;
    int lim = b * CH;
    int s = 0;
    for (int i = t; i < lim; i += 256) s += g_hist[i];
    sd[t] = s; __syncthreads();
    for (int o = 128; o; o >>= 1) { if (t < o) sd[t] += sd[t + o]; __syncthreads(); }
    if (t == 0) sbase = sd[0];
    __syncthreads();
    int chunkbase = sbase;
    __syncthreads();
    int idx = b * CH + t * 4;
    int h0 = (idx + 0 < NN) ? g_hist[idx + 0] : 0;
    int h1 = (idx + 1 < NN) ? g_hist[idx + 1] : 0;
    int h2 = (idx + 2 < NN) ? g_hist[idx + 2] : 0;
    int h3 = (idx + 3 < NN) ? g_hist[idx + 3] : 0;
    int sum = h0 + h1 + h2 + h3;
    sd[t] = sum; __syncthreads();
    for (int o = 1; o < 256; o <<= 1) {
        int v = (t >= o) ? sd[t - o] : 0;
        __syncthreads();
        sd[t] += v;
        __syncthreads();
    }
    int base = chunkbase + sd[t] - sum;
    if (idx + 0 < NN) g_off[idx + 0] = base;
    if (idx + 1 < NN) g_off[idx + 1] = base + h0;
    if (idx + 2 < NN) g_off[idx + 2] = base + h0 + h1;
    if (idx + 3 < NN) g_off[idx + 3] = base + h0 + h1 + h2;
}
__global__ void scatter_sort_kernel(const int* __restrict__ src_idx,
                                    const int* __restrict__ dst_idx,
                                    const int* __restrict__ rel_idx,
                                    const int* __restrict__ rel_time,
                                    const int* __restrict__ batch_idx) {
    int e = blockIdx.x * blockDim.x + threadIdx.x;
    if (e >= NE) return;
    int src = src_idx[e];
    int rt  = rel_time[e];
    int cls = rt > 0 ? 2 : (rt == 0 ? 1 : 0);  // 0=past(Wp) 1=now(Wn) 2=future(Wf)
    int ta  = rt < 0 ? -rt : rt;
    int rel = rel_idx[e];
    int pos = atomicAdd(&g_off[src], 1);
    g_eMeta[pos] = make_int2(src | (cls << 17) | (ta << 19),
                             dst_idx[e] | (rel << 17) | (batch_idx[e] << 25));
}

// ---------------- ALL per-layer tables in one launch ----------------
__global__ void tables_all_kernel(const float* __restrict__ rela,
                                  const float* __restrict__ timeE,
                                  const float* __restrict__ Wp,
                                  const float* __restrict__ Wn,
                                  const float* __restrict__ Wf,
                                  const float* __restrict__ W1,
                                  const float* __restrict__ W2,
                                  const int* __restrict__ query_rel) {
    int w = (blockIdx.x * blockDim.x + threadIdx.x) >> 5;
    int lane = threadIdx.x & 31;
    if (w < RWROWS + TWROWS) {
        const float* in; __half2* out; int cls;
        if (w < RWROWS) {
            int layer = w / (3 * NRELP);
            int r2 = w % (3 * NRELP);
            cls = r2 / NRELP;
            in = rela + (layer * NRELP + (r2 % NRELP)) * NH;
            out = g_RWh + w * 32;
        } else {
            int w2 = w - RWROWS;
            cls = w2 / NTA;
            in = timeE + (w2 % NTA) * NH;
            out = g_TWh + w2 * 32;
        }
        const float* W = (cls == 0) ? Wp : ((cls == 1) ? Wn : Wf);
        float2 ev = __ldg((const float2*)&in[2 * lane]);
        int h0 = 2 * lane;
        float a0 = 0.f, a1 = 0.f;
#pragma unroll 8
        for (int k2 = 0; k2 < 32; ++k2) {
            float bx = __shfl_sync(FULLM, ev.x, k2);
            float by = __shfl_sync(FULLM, ev.y, k2);
            float2 w0 = __ldg((const float2*)&W[h0 * 64 + 2 * k2]);
            float2 w1 = __ldg((const float2*)&W[(h0 + 1) * 64 + 2 * k2]);
            a0 += bx * w0.x + by * w0.y;
            a1 += bx * w1.x + by * w1.y;
        }
        out[lane] = __floats2half2_rn(a0, a1);
        return;
    }
    int wq = w - (RWROWS + TWROWS);
    if (wq >= NL * RQROWS) return;
    int layer = wq / RQROWS;
    int rr = wq % RQROWS;
    int b = rr / NRELP, r = rr % NRELP;
    const float* relaL = rela + layer * NRELP * NH;
    const float* W1L = W1 + layer * 5 * 192;
    int qrb = __ldg(&query_rel[b]);
    float2 re = __ldg((const float2*)&relaL[r * 64 + 2 * lane]);
    float2 qe = __ldg((const float2*)&relaL[qrb * 64 + 2 * lane]);
    float p[5];
#pragma unroll
    for (int a = 0; a < 5; ++a) {
        float2 v  = __ldg((const float2*)&W1L[a * 192 + 64 + 2 * lane]);
        float2 ww = __ldg((const float2*)&W1L[a * 192 + 128 + 2 * lane]);
        p[a] = re.x * v.x + re.y * v.y + qe.x * ww.x + qe.y * ww.y;
    }
#pragma unroll
    for (int a = 0; a < 5; ++a)
#pragma unroll
        for (int off = 16; off; off >>= 1) p[a] += __shfl_xor_sync(FULLM, p[a], off);
    if (lane == 0) {
#pragma unroll
        for (int a = 0; a < 5; ++a) g_rq[wq * 8 + a] = p[a];
        if (layer == 0) {
            float z = 0.f;
#pragma unroll
            for (int a = 0; a < 5; ++a) z += fmaxf(p[a], 0.f) * __ldg(&W2[a]);
            g_score0[rr] = 1.f / (1.f + __expf(-z));
        }
    }
}

// hW[cls][node] = relu(g_next)[node] @ W_cls^T -> fp16; cls==0 blocks also emit hv
__global__ void __launch_bounds__(256) hw_kernel(const float* __restrict__ Wp,
                                                 const float* __restrict__ Wn,
                                                 const float* __restrict__ Wf,
                                                 const float* __restrict__ W1L) {
    extern __shared__ float dyn[];
    float* sW = dyn;            // 4352 floats
    float* sT = dyn + 4352;     // 128*66 floats
    float* sU = dyn + 4352 + 128 * 66;  // 5*64 floats
    int cls = blockIdx.y;
    const float* W = (cls == 0) ? Wp : ((cls == 1) ? Wn : Wf);
    int t = threadIdx.x;
    for (int idx = t; idx < 4096; idx += 256) {
        int h = idx >> 6, k = idx & 63;
        sW[k * 68 + h + (h >= 32 ? 4 : 0)] = __ldg(&W[h * 64 + k]);
    }
    if (cls == 0) {
        for (int idx = t; idx < 5 * 64; idx += 256) {
            int a = idx >> 6, k = idx & 63;
            sU[idx] = __ldg(&W1L[a * 192 + k]);
        }
    }
    __syncthreads();
    for (int tile = blockIdx.x * 128; tile < NN; tile += gridDim.x * 128) {
        int nN = min(128, NN - tile);
        for (int j = t; j < nN * 32; j += 256) {
            int nl = j >> 5, l = j & 31;
            float2 v = *(const float2*)&g_next[(size_t)(tile + nl) * 64 + 2 * l];
            v.x = fmaxf(v.x, 0.f); v.y = fmaxf(v.y, 0.f);   // relu inline
            *(float2*)&sT[nl * 66 + 2 * l] = v;
        }
        __syncthreads();
        int slot = t >> 1, p = t & 1;
        if (slot < nN) {
            if (cls == 0) {
                const float* row = sT + slot * 66 + p * 32;
                float pa[5] = {0.f, 0.f, 0.f, 0.f, 0.f};
#pragma unroll 8
                for (int k = 0; k < 32; ++k) {
                    float hk = row[k];
#pragma unroll
                    for (int a = 0; a < 5; ++a) pa[a] += hk * sU[a * 64 + p * 32 + k];
                }
#pragma unroll
                for (int a = 0; a < 5; ++a) pa[a] += __shfl_xor_sync(FULLM, pa[a], 1);
                if (p == 0) {
                    float* hvp = g_hv + (size_t)(tile + slot) * 8;
                    *(float4*)hvp = make_float4(pa[0], pa[1], pa[2], pa[3]);
                    hvp[4] = pa[4];
                }
            }
            const float* wb = sW + p * 36;
            const float* er = sT + slot * 66;
            ull acc[16];
#pragma unroll
            for (int j = 0; j < 16; ++j) acc[j] = 0ull;
#pragma unroll 4
            for (int k2 = 0; k2 < 32; ++k2) {
                float2 e2 = *(const float2*)&er[2 * k2];
                ull b0 = dup_f(e2.x);
                ull b1 = dup_f(e2.y);
                const float* r0 = wb + (2 * k2) * 68;
                const float* r1 = r0 + 68;
#pragma unroll
                for (int j = 0; j < 8; ++j) {
                    ulonglong2 w0 = *(const ulonglong2*)(r0 + 4 * j);
                    FMA2(acc[2 * j],     w0.x, b0, acc[2 * j]);
                    FMA2(acc[2 * j + 1], w0.y, b0, acc[2 * j + 1]);
                }
#pragma unroll
                for (int j = 0; j < 8; ++j) {
                    ulonglong2 w1 = *(const ulonglong2*)(r1 + 4 * j);
                    FMA2(acc[2 * j],     w1.x, b1, acc[2 * j]);
                    FMA2(acc[2 * j + 1], w1.y, b1, acc[2 * j + 1]);
                }
            }
            __half2 hh[16];
#pragma unroll
            for (int j = 0; j < 16; ++j) {
                float2 f = *(float2*)&acc[j];
                hh[j] = __float22half2_rn(f);
            }
            __half2* ob = g_hWh + ((size_t)cls * NN + tile + slot) * 32 + p * 16;
#pragma unroll
            for (int j = 0; j < 4; ++j)
                *(uint4*)(ob + 4 * j) = *(uint4*)(hh + 4 * j);
        }
        __syncthreads();
    }
}

// ---------------- per-edge score (layers > 0), 2 edges per thread ----------------
__global__ void score_kernel(const float* __restrict__ W2L, int layer) {
    int i = blockIdx.x * blockDim.x + threadIdx.x;
    int e0 = 2 * i;
    if (e0 >= NE) return;
    const float* rqL = g_rq + (size_t)layer * RQROWS * 8;
    int4 mm = __ldg((const int4*)&g_eMeta[e0]);   // two int2 metas
    float w20 = __ldg(&W2L[0]), w21 = __ldg(&W2L[1]), w22 = __ldg(&W2L[2]);
    float w23 = __ldg(&W2L[3]), w24 = __ldg(&W2L[4]);
    float sc[2];
#pragma unroll
    for (int k = 0; k < 2; ++k) {
        int mx = k ? mm.z : mm.x;
        int my = k ? mm.w : mm.y;
        int src = mx & 0x1FFFF;
        int rel = (my >> 17) & 0xFF;
        int b   = (my >> 25) & 0x1F;
        const float4* rq4 = (const float4*)&rqL[(b * NRELP + rel) * 8];
        float4 r0 = __ldg(&rq4[0]); float4 r1 = __ldg(&rq4[1]);
        const float4* hv4 = (const float4*)&g_hv[src * 8];
        float4 h0 = __ldg(&hv4[0]); float4 h1 = __ldg(&hv4[1]);
        float z = fmaxf(r0.x + h0.x, 0.f) * w20 + fmaxf(r0.y + h0.y, 0.f) * w21
                + fmaxf(r0.z + h0.z, 0.f) * w22 + fmaxf(r0.w + h0.w, 0.f) * w23
                + fmaxf(r1.x + h1.x, 0.f) * w24;
        sc[k] = 1.f / (1.f + __expf(-z));
    }
    *(float2*)&g_score[e0] = make_float2(sc[0], sc[1]);
}

// ---------------- main edge kernel (half-warp per edge, fp16 tables) ----------------
__global__ void __launch_bounds__(256) edge_kernel(int layer) {
    int gw = (blockIdx.x * blockDim.x + threadIdx.x) >> 5;
    int lane = threadIdx.x & 31;
    int half = lane >> 4;
    int hl = lane & 15;
    int nw = (gridDim.x * blockDim.x) >> 5;
    const __half2* RWl = g_RWh + (size_t)layer * (3 * NRELP) * 32;
    int isL0 = (layer == 0);
    for (int base = gw * 8; base < NE; base += nw * 8) {
#pragma unroll
        for (int p = 0; p < 4; ++p) {
            int e = base + 2 * p + half;
            int2 m = __ldg(&g_eMeta[e]);
            int src = m.x & 0x1FFFF;
            int cls = (m.x >> 17) & 3;
            int ta  = (m.x >> 19) & 0x1FF;
            int dst = m.y & 0x1FFFF;
            int rel = (m.y >> 17) & 0xFF;
            float s;
            if (isL0) {
                int b = (m.y >> 25) & 0x1F;
                s = __ldg(&g_score0[b * NRELP + rel]);
            } else {
                s = __ldg(&g_score[e]);
            }
            uint2 ra = __ldg((const uint2*)(RWl + (cls * NRELP + rel) * 32 + 2 * hl));
            uint2 tb = __ldg((const uint2*)(g_TWh + (cls * NTA + ta) * 32 + 2 * hl));
            __half2 t0 = __hadd2(*(__half2*)&ra.x, *(__half2*)&tb.x);
            __half2 t1 = __hadd2(*(__half2*)&ra.y, *(__half2*)&tb.y);
            if (!isL0) {
                uint2 hw = __ldg((const uint2*)(g_hWh + ((size_t)cls * NN + src) * 32 + 2 * hl));
                t0 = __hadd2(t0, *(__half2*)&hw.x);
                t1 = __hadd2(t1, *(__half2*)&hw.y);
            }
            float2 f01 = __half22float2(t0);
            float2 f23 = __half22float2(t1);
            red4(&g_next[(size_t)dst * 64 + 4 * hl], s * f01.x, s * f01.y, s * f23.x, s * f23.y);
        }
    }
}

// ---------------- output: relu(g_next).Wc + bc ----------------
__global__ void out_kernel(const float* __restrict__ Wc, const float* __restrict__ bc,
                           const int* __restrict__ ob, const int* __restrict__ oe,
                           float* __restrict__ out) {
    int gw = (blockIdx.x * blockDim.x + threadIdx.x) >> 5;
    int lane = threadIdx.x & 31;
    if (gw >= NN) return;
    float2 h = *(const float2*)&g_next[(size_t)gw * 64 + 2 * lane];
    h.x = fmaxf(h.x, 0.f); h.y = fmaxf(h.y, 0.f);
    float2 w = __ldg((const float2*)&Wc[2 * lane]);
    float p = h.x * w.x + h.y * w.y;
#pragma unroll
    for (int off = 16; off; off >>= 1) p += __shfl_xor_sync(FULLM, p, off);
    if (lane == 0) out[ob[gw] * NENT + oe[gw]] = p + bc[0];
}

// ---------------- host launch ----------------
extern "C" void kernel_launch(void* const* d_in, const int* in_sizes, int n_in,
                              void* d_out, int out_size) {
    const int *bt, *si, *di, *ri, *rt, *qr, *ob, *oe;
    const float *rela, *te, *Wp, *Wn, *Wf, *W1, *W2, *Wc, *bc;

    if (in_sizes[0] == NE) {
        bt = (const int*)d_in[0];  si = (const int*)d_in[1];
        di = (const int*)d_in[2];  ri = (const int*)d_in[3];
        rt = (const int*)d_in[4];  qr = (const int*)d_in[5];
        ob = (const int*)d_in[6];  oe = (const int*)d_in[7];
        rela = (const float*)d_in[8];  te = (const float*)d_in[9];
        Wp = (const float*)d_in[10]; Wn = (const float*)d_in[11];
        Wf = (const float*)d_in[12]; W1 = (const float*)d_in[13];
        W2 = (const float*)d_in[14]; Wc = (const float*)d_in[15];
        bc = (const float*)d_in[16];
    } else {
        rela = (const float*)d_in[0];  te = (const float*)d_in[1];
        Wp = (const float*)d_in[2]; Wn = (const float*)d_in[3];
        Wf = (const float*)d_in[4]; W1 = (const float*)d_in[5];
        W2 = (const float*)d_in[6]; Wc = (const float*)d_in[7];
        bc = (const float*)d_in[8];
        bt = (const int*)d_in[9];  si = (const int*)d_in[10];
        di = (const int*)d_in[11]; ri = (const int*)d_in[12];
        rt = (const int*)d_in[13]; qr = (const int*)d_in[14];
        ob = (const int*)d_in[15]; oe = (const int*)d_in[16];
    }

    float* out = (float*)d_out;

    static int attr_done = 0;
    const int hw_smem = (4352 + 128 * 66 + 5 * 64) * 4;   // 52480 B
    if (!attr_done) {
        cudaFuncSetAttribute(hw_kernel, cudaFuncAttributeMaxDynamicSharedMemorySize, hw_smem);
        attr_done = 1;
    }

    const int n4 = NN * NH / 4;

    init_kernel<<<1600, 256>>>(out, out_size);

    // ALL per-layer tables in one latency wave
    const int tot_warps = RWROWS + TWROWS + NL * RQROWS;   // 25350
    tables_all_kernel<<<(tot_warps * 32 + 255) / 256, 256>>>(
        rela, te, Wp, Wn, Wf, W1, W2, qr);

    // counting sort by src
    hist_kernel<<<(NE + 255) / 256, 256>>>(si);
    offscan_kernel<<<NCHUNK, 256>>>();
    scatter_sort_kernel<<<(NE + 255) / 256, 256>>>(si, di, ri, rt, bt);

    for (int layer = 0; layer < NL; ++layer) {
        const float* W1L = W1 + layer * 5 * 192;
        const float* W2L = W2 + layer * 5;
        if (layer > 0) {
            hw_kernel<<<dim3((NN + 127) / 128, 3), 256, hw_smem>>>(Wp, Wn, Wf, W1L);
            zero_next_kernel<<<(n4 + 255) / 256, 256>>>();
            score_kernel<<<(NE / 2 + 255) / 256, 256>>>(W2L, layer);
        }
        edge_kernel<<<1184, 256>>>(layer);
    }

    out_kernel<<<(NN * 32 + 255) / 256, 256>>>(Wc, bc, ob, oe, out);
}

// round 15
// speedup vs baseline: 1.2570x; 1.0146x over previous
#include <cuda_runtime.h>
#include <cuda_fp16.h>

#define NB 32
#define NN 100000
#define NE 1000000
#define NH 64
#define NL 3
#define NRELP 231
#define NTA 365
#define NENT 7128
#define FULLM 0xffffffffu
#define CH 1024
#define NCHUNK 98   // ceil(NN/CH)
#define RWROWS (NL * 3 * NRELP)     // 2079
#define TWROWS (3 * NTA)            // 1095
#define RQROWS (NB * NRELP)         // 7392

typedef unsigned long long ull;

// ---------------- device scratch ----------------
static __device__ float   g_next[NN * NH];                       // 25.6 MB (pre-relu aggregate)
static __device__ __align__(16) __half2 g_hWh[3 * NN * 32];      // 38.4 MB transformed hidden (fp16)
static __device__ __align__(16) __half2 g_RWh[RWROWS * 32];      // [layer][cls][rel] rela @ W^T (fp16)
static __device__ __align__(16) __half2 g_TWh[TWROWS * 32];      // [cls][ta] time @ W^T (fp16)
static __device__ __align__(16) int2 g_eMeta[NE];   // {src|cls<<17|ta<<19, dst|rel<<17|b<<25}
static __device__ __align__(8) float g_score[NE];
static __device__ float   g_score0[RQROWS];         // layer-0 score table (hidden=0)
static __device__ float   g_hv[NN * 8];
static __device__ float   g_rq[NL * RQROWS * 8];    // [layer][b*NRELP+rel][8]
static __device__ int     g_hist[NN];
static __device__ int     g_off[NN];
static __device__ int     g_part[NCHUNK];

#define FMA2(d, a, b, c) \
    asm("fma.rn.f32x2 %0, %1, %2, %3;" : "=l"(d) : "l"(a), "l"(b), "l"(c))

__device__ __forceinline__ ull dup_f(float x) {
    ull r; unsigned u = __float_as_uint(x);
    asm("mov.b64 %0, {%1, %1};" : "=l"(r) : "r"(u));
    return r;
}
__device__ __forceinline__ void red4(float* p, float x, float y, float z, float w) {
    asm volatile("red.global.add.v4.f32 [%0], {%1, %2, %3, %4};"
                 :: "l"(p), "f"(x), "f"(y), "f"(z), "f"(w) : "memory");
}

// ---------------- fused init: g_next, g_hist, out ----------------
__global__ void init_kernel(float* out, int n_out) {
    int i = blockIdx.x * blockDim.x + threadIdx.x;
    int stride = gridDim.x * blockDim.x;
    const int n4 = NN * NH / 4;
    for (int j = i; j < n4; j += stride)
        ((float4*)g_next)[j] = make_float4(0.f, 0.f, 0.f, 0.f);
    for (int j = i; j < NN; j += stride) g_hist[j] = 0;
    for (int j = i; j < n_out; j += stride) out[j] = 0.f;
}

// ---------------- zero g_next (between layers, after hw consumed it) ----------------
__global__ void zero_next_kernel() {
    int i = blockIdx.x * blockDim.x + threadIdx.x;
    const int n4 = NN * NH / 4;
    if (i < n4) ((float4*)g_next)[i] = make_float4(0.f, 0.f, 0.f, 0.f);
}

// ---------------- counting sort by src ----------------
__global__ void hist_kernel(const int* __restrict__ src_idx) {
    int e = blockIdx.x * blockDim.x + threadIdx.x;
    if (e < NE) atomicAdd(&g_hist[src_idx[e]], 1);
}
// phase 1: per-chunk sums (98 blocks, 4 loads/thread)
__global__ void sum_chunk_kernel() {
    __shared__ int sd[256];
    int b = blockIdx.x, t = threadIdx.x;
    int idx = b * CH + t * 4;
    int s = 0;
    if (idx + 0 < NN) s += g_hist[idx + 0];
    if (idx + 1 < NN) s += g_hist[idx + 1];
    if (idx + 2 < NN) s += g_hist[idx + 2];
    if (idx + 3 < NN) s += g_hist[idx + 3];
    sd[t] = s; __syncthreads();
    for (int o = 128; o; o >>= 1) { if (t < o) sd[t] += sd[t + o]; __syncthreads(); }
    if (t == 0) g_part[b] = sd[0];
}
// phase 2: prefix over 98 chunk partials (warp-cheap) + in-chunk scan
__global__ void offscan_kernel() {
    __shared__ int sd[256];
    __shared__ int sbase;
    int b = blockIdx.x, t = threadIdx.x;
    if (t < 32) {
        int s = 0;
        for (int i = t; i < b; i += 32) s += g_part[i];
#pragma unroll
        for (int o = 16; o; o >>= 1) s += __shfl_xor_sync(FULLM, s, o);
        if (t == 0) sbase = s;
    }
    __syncthreads();
    int chunkbase = sbase;
    int idx = b * CH + t * 4;
    int h0 = (idx + 0 < NN) ? g_hist[idx + 0] : 0;
    int h1 = (idx + 1 < NN) ? g_hist[idx + 1] : 0;
    int h2 = (idx + 2 < NN) ? g_hist[idx + 2] : 0;
    int h3 = (idx + 3 < NN) ? g_hist[idx + 3] : 0;
    int sum = h0 + h1 + h2 + h3;
    sd[t] = sum; __syncthreads();
    for (int o = 1; o < 256; o <<= 1) {
        int v = (t >= o) ? sd[t - o] : 0;
        __syncthreads();
        sd[t] += v;
        __syncthreads();
    }
    int base = chunkbase + sd[t] - sum;
    if (idx + 0 < NN) g_off[idx + 0] = base;
    if (idx + 1 < NN) g_off[idx + 1] = base + h0;
    if (idx + 2 < NN) g_off[idx + 2] = base + h0 + h1;
    if (idx + 3 < NN) g_off[idx + 3] = base + h0 + h1 + h2;
}
__global__ void scatter_sort_kernel(const int* __restrict__ src_idx,
                                    const int* __restrict__ dst_idx,
                                    const int* __restrict__ rel_idx,
                                    const int* __restrict__ rel_time,
                                    const int* __restrict__ batch_idx) {
    int e = blockIdx.x * blockDim.x + threadIdx.x;
    if (e >= NE) return;
    int src = src_idx[e];
    int rt  = rel_time[e];
    int cls = rt > 0 ? 2 : (rt == 0 ? 1 : 0);  // 0=past(Wp) 1=now(Wn) 2=future(Wf)
    int ta  = rt < 0 ? -rt : rt;
    int rel = rel_idx[e];
    int pos = atomicAdd(&g_off[src], 1);
    g_eMeta[pos] = make_int2(src | (cls << 17) | (ta << 19),
                             dst_idx[e] | (rel << 17) | (batch_idx[e] << 25));
}

// ---------------- ALL per-layer tables in one launch ----------------
__global__ void tables_all_kernel(const float* __restrict__ rela,
                                  const float* __restrict__ timeE,
                                  const float* __restrict__ Wp,
                                  const float* __restrict__ Wn,
                                  const float* __restrict__ Wf,
                                  const float* __restrict__ W1,
                                  const float* __restrict__ W2,
                                  const int* __restrict__ query_rel) {
    int w = (blockIdx.x * blockDim.x + threadIdx.x) >> 5;
    int lane = threadIdx.x & 31;
    if (w < RWROWS + TWROWS) {
        const float* in; __half2* out; int cls;
        if (w < RWROWS) {
            int layer = w / (3 * NRELP);
            int r2 = w % (3 * NRELP);
            cls = r2 / NRELP;
            in = rela + (layer * NRELP + (r2 % NRELP)) * NH;
            out = g_RWh + w * 32;
        } else {
            int w2 = w - RWROWS;
            cls = w2 / NTA;
            in = timeE + (w2 % NTA) * NH;
            out = g_TWh + w2 * 32;
        }
        const float* W = (cls == 0) ? Wp : ((cls == 1) ? Wn : Wf);
        float2 ev = __ldg((const float2*)&in[2 * lane]);
        int h0 = 2 * lane;
        float a0 = 0.f, a1 = 0.f;
#pragma unroll 8
        for (int k2 = 0; k2 < 32; ++k2) {
            float bx = __shfl_sync(FULLM, ev.x, k2);
            float by = __shfl_sync(FULLM, ev.y, k2);
            float2 w0 = __ldg((const float2*)&W[h0 * 64 + 2 * k2]);
            float2 w1 = __ldg((const float2*)&W[(h0 + 1) * 64 + 2 * k2]);
            a0 += bx * w0.x + by * w0.y;
            a1 += bx * w1.x + by * w1.y;
        }
        out[lane] = __floats2half2_rn(a0, a1);
        return;
    }
    int wq = w - (RWROWS + TWROWS);
    if (wq >= NL * RQROWS) return;
    int layer = wq / RQROWS;
    int rr = wq % RQROWS;
    int b = rr / NRELP, r = rr % NRELP;
    const float* relaL = rela + layer * NRELP * NH;
    const float* W1L = W1 + layer * 5 * 192;
    int qrb = __ldg(&query_rel[b]);
    float2 re = __ldg((const float2*)&relaL[r * 64 + 2 * lane]);
    float2 qe = __ldg((const float2*)&relaL[qrb * 64 + 2 * lane]);
    float p[5];
#pragma unroll
    for (int a = 0; a < 5; ++a) {
        float2 v  = __ldg((const float2*)&W1L[a * 192 + 64 + 2 * lane]);
        float2 ww = __ldg((const float2*)&W1L[a * 192 + 128 + 2 * lane]);
        p[a] = re.x * v.x + re.y * v.y + qe.x * ww.x + qe.y * ww.y;
    }
#pragma unroll
    for (int a = 0; a < 5; ++a)
#pragma unroll
        for (int off = 16; off; off >>= 1) p[a] += __shfl_xor_sync(FULLM, p[a], off);
    if (lane == 0) {
#pragma unroll
        for (int a = 0; a < 5; ++a) g_rq[wq * 8 + a] = p[a];
        if (layer == 0) {
            float z = 0.f;
#pragma unroll
            for (int a = 0; a < 5; ++a) z += fmaxf(p[a], 0.f) * __ldg(&W2[a]);
            g_score0[rr] = 1.f / (1.f + __expf(-z));
        }
    }
}

// hW[cls][node] = relu(g_next)[node] @ W_cls^T -> fp16; cls==0 blocks also emit hv
__global__ void __launch_bounds__(256) hw_kernel(const float* __restrict__ Wp,
                                                 const float* __restrict__ Wn,
                                                 const float* __restrict__ Wf,
                                                 const float* __restrict__ W1L) {
    extern __shared__ float dyn[];
    float* sW = dyn;            // 4352 floats
    float* sT = dyn + 4352;     // 128*66 floats
    float* sU = dyn + 4352 + 128 * 66;  // 5*64 floats
    int cls = blockIdx.y;
    const float* W = (cls == 0) ? Wp : ((cls == 1) ? Wn : Wf);
    int t = threadIdx.x;
    for (int idx = t; idx < 4096; idx += 256) {
        int h = idx >> 6, k = idx & 63;
        sW[k * 68 + h + (h >= 32 ? 4 : 0)] = __ldg(&W[h * 64 + k]);
    }
    if (cls == 0) {
        for (int idx = t; idx < 5 * 64; idx += 256) {
            int a = idx >> 6, k = idx & 63;
            sU[idx] = __ldg(&W1L[a * 192 + k]);
        }
    }
    __syncthreads();
    for (int tile = blockIdx.x * 128; tile < NN; tile += gridDim.x * 128) {
        int nN = min(128, NN - tile);
        for (int j = t; j < nN * 32; j += 256) {
            int nl = j >> 5, l = j & 31;
            float2 v = *(const float2*)&g_next[(size_t)(tile + nl) * 64 + 2 * l];
            v.x = fmaxf(v.x, 0.f); v.y = fmaxf(v.y, 0.f);   // relu inline
            *(float2*)&sT[nl * 66 + 2 * l] = v;
        }
        __syncthreads();
        int slot = t >> 1, p = t & 1;
        if (slot < nN) {
            if (cls == 0) {
                const float* row = sT + slot * 66 + p * 32;
                float pa[5] = {0.f, 0.f, 0.f, 0.f, 0.f};
#pragma unroll 8
                for (int k = 0; k < 32; ++k) {
                    float hk = row[k];
#pragma unroll
                    for (int a = 0; a < 5; ++a) pa[a] += hk * sU[a * 64 + p * 32 + k];
                }
#pragma unroll
                for (int a = 0; a < 5; ++a) pa[a] += __shfl_xor_sync(FULLM, pa[a], 1);
                if (p == 0) {
                    float* hvp = g_hv + (size_t)(tile + slot) * 8;
                    *(float4*)hvp = make_float4(pa[0], pa[1], pa[2], pa[3]);
                    hvp[4] = pa[4];
                }
            }
            const float* wb = sW + p * 36;
            const float* er = sT + slot * 66;
            ull acc[16];
#pragma unroll
            for (int j = 0; j < 16; ++j) acc[j] = 0ull;
#pragma unroll 4
            for (int k2 = 0; k2 < 32; ++k2) {
                float2 e2 = *(const float2*)&er[2 * k2];
                ull b0 = dup_f(e2.x);
                ull b1 = dup_f(e2.y);
                const float* r0 = wb + (2 * k2) * 68;
                const float* r1 = r0 + 68;
#pragma unroll
                for (int j = 0; j < 8; ++j) {
                    ulonglong2 w0 = *(const ulonglong2*)(r0 + 4 * j);
                    FMA2(acc[2 * j],     w0.x, b0, acc[2 * j]);
                    FMA2(acc[2 * j + 1], w0.y, b0, acc[2 * j + 1]);
                }
#pragma unroll
                for (int j = 0; j < 8; ++j) {
                    ulonglong2 w1 = *(const ulonglong2*)(r1 + 4 * j);
                    FMA2(acc[2 * j],     w1.x, b1, acc[2 * j]);
                    FMA2(acc[2 * j + 1], w1.y, b1, acc[2 * j + 1]);
                }
            }
            __half2 hh[16];
#pragma unroll
            for (int j = 0; j < 16; ++j) {
                float2 f = *(float2*)&acc[j];
                hh[j] = __float22half2_rn(f);
            }
            __half2* ob = g_hWh + ((size_t)cls * NN + tile + slot) * 32 + p * 16;
#pragma unroll
            for (int j = 0; j < 4; ++j)
                *(uint4*)(ob + 4 * j) = *(uint4*)(hh + 4 * j);
        }
        __syncthreads();
    }
}

// ---------------- per-edge score (layers > 0), 2 edges per thread ----------------
__global__ void score_kernel(const float* __restrict__ W2L, int layer) {
    int i = blockIdx.x * blockDim.x + threadIdx.x;
    int e0 = 2 * i;
    if (e0 >= NE) return;
    const float* rqL = g_rq + (size_t)layer * RQROWS * 8;
    int4 mm = __ldg((const int4*)&g_eMeta[e0]);   // two int2 metas
    float w20 = __ldg(&W2L[0]), w21 = __ldg(&W2L[1]), w22 = __ldg(&W2L[2]);
    float w23 = __ldg(&W2L[3]), w24 = __ldg(&W2L[4]);
    float sc[2];
#pragma unroll
    for (int k = 0; k < 2; ++k) {
        int mx = k ? mm.z : mm.x;
        int my = k ? mm.w : mm.y;
        int src = mx & 0x1FFFF;
        int rel = (my >> 17) & 0xFF;
        int b   = (my >> 25) & 0x1F;
        const float4* rq4 = (const float4*)&rqL[(b * NRELP + rel) * 8];
        float4 r0 = __ldg(&rq4[0]); float4 r1 = __ldg(&rq4[1]);
        const float4* hv4 = (const float4*)&g_hv[src * 8];
        float4 h0 = __ldg(&hv4[0]); float4 h1 = __ldg(&hv4[1]);
        float z = fmaxf(r0.x + h0.x, 0.f) * w20 + fmaxf(r0.y + h0.y, 0.f) * w21
                + fmaxf(r0.z + h0.z, 0.f) * w22 + fmaxf(r0.w + h0.w, 0.f) * w23
                + fmaxf(r1.x + h1.x, 0.f) * w24;
        sc[k] = 1.f / (1.f + __expf(-z));
    }
    *(float2*)&g_score[e0] = make_float2(sc[0], sc[1]);
}

// ---------------- main edge kernel (half-warp per edge, fp16 tables) ----------------
__global__ void __launch_bounds__(256) edge_kernel(int layer) {
    int gw = (blockIdx.x * blockDim.x + threadIdx.x) >> 5;
    int lane = threadIdx.x & 31;
    int half = lane >> 4;
    int hl = lane & 15;
    int nw = (gridDim.x * blockDim.x) >> 5;
    const __half2* RWl = g_RWh + (size_t)layer * (3 * NRELP) * 32;
    int isL0 = (layer == 0);
    for (int base = gw * 8; base < NE; base += nw * 8) {
#pragma unroll
        for (int p = 0; p < 4; ++p) {
            int e = base + 2 * p + half;
            int2 m = __ldg(&g_eMeta[e]);
            int src = m.x & 0x1FFFF;
            int cls = (m.x >> 17) & 3;
            int ta  = (m.x >> 19) & 0x1FF;
            int dst = m.y & 0x1FFFF;
            int rel = (m.y >> 17) & 0xFF;
            float s;
            if (isL0) {
                int b = (m.y >> 25) & 0x1F;
                s = __ldg(&g_score0[b * NRELP + rel]);
            } else {
                s = __ldg(&g_score[e]);
            }
            uint2 ra = __ldg((const uint2*)(RWl + (cls * NRELP + rel) * 32 + 2 * hl));
            uint2 tb = __ldg((const uint2*)(g_TWh + (cls * NTA + ta) * 32 + 2 * hl));
            __half2 t0 = __hadd2(*(__half2*)&ra.x, *(__half2*)&tb.x);
            __half2 t1 = __hadd2(*(__half2*)&ra.y, *(__half2*)&tb.y);
            if (!isL0) {
                uint2 hw = __ldg((const uint2*)(g_hWh + ((size_t)cls * NN + src) * 32 + 2 * hl));
                t0 = __hadd2(t0, *(__half2*)&hw.x);
                t1 = __hadd2(t1, *(__half2*)&hw.y);
            }
            float2 f01 = __half22float2(t0);
            float2 f23 = __half22float2(t1);
            red4(&g_next[(size_t)dst * 64 + 4 * hl], s * f01.x, s * f01.y, s * f23.x, s * f23.y);
        }
    }
}

// ---------------- output: relu(g_next).Wc + bc ----------------
__global__ void out_kernel(const float* __restrict__ Wc, const float* __restrict__ bc,
                           const int* __restrict__ ob, const int* __restrict__ oe,
                           float* __restrict__ out) {
    int gw = (blockIdx.x * blockDim.x + threadIdx.x) >> 5;
    int lane = threadIdx.x & 31;
    if (gw >= NN) return;
    float2 h = *(const float2*)&g_next[(size_t)gw * 64 + 2 * lane];
    h.x = fmaxf(h.x, 0.f); h.y = fmaxf(h.y, 0.f);
    float2 w = __ldg((const float2*)&Wc[2 * lane]);
    float p = h.x * w.x + h.y * w.y;
#pragma unroll
    for (int off = 16; off; off >>= 1) p += __shfl_xor_sync(FULLM, p, off);
    if (lane == 0) out[ob[gw] * NENT + oe[gw]] = p + bc[0];
}

// ---------------- host launch ----------------
extern "C" void kernel_launch(void* const* d_in, const int* in_sizes, int n_in,
                              void* d_out, int out_size) {
    const int *bt, *si, *di, *ri, *rt, *qr, *ob, *oe;
    const float *rela, *te, *Wp, *Wn, *Wf, *W1, *W2, *Wc, *bc;

    if (in_sizes[0] == NE) {
        bt = (const int*)d_in[0];  si = (const int*)d_in[1];
        di = (const int*)d_in[2];  ri = (const int*)d_in[3];
        rt = (const int*)d_in[4];  qr = (const int*)d_in[5];
        ob = (const int*)d_in[6];  oe = (const int*)d_in[7];
        rela = (const float*)d_in[8];  te = (const float*)d_in[9];
        Wp = (const float*)d_in[10]; Wn = (const float*)d_in[11];
        Wf = (const float*)d_in[12]; W1 = (const float*)d_in[13];
        W2 = (const float*)d_in[14]; Wc = (const float*)d_in[15];
        bc = (const float*)d_in[16];
    } else {
        rela = (const float*)d_in[0];  te = (const float*)d_in[1];
        Wp = (const float*)d_in[2]; Wn = (const float*)d_in[3];
        Wf = (const float*)d_in[4]; W1 = (const float*)d_in[5];
        W2 = (const float*)d_in[6]; Wc = (const float*)d_in[7];
        bc = (const float*)d_in[8];
        bt = (const int*)d_in[9];  si = (const int*)d_in[10];
        di = (const int*)d_in[11]; ri = (const int*)d_in[12];
        rt = (const int*)d_in[13]; qr = (const int*)d_in[14];
        ob = (const int*)d_in[15]; oe = (const int*)d_in[16];
    }

    float* out = (float*)d_out;

    static int attr_done = 0;
    const int hw_smem = (4352 + 128 * 66 + 5 * 64) * 4;   // 52480 B
    if (!attr_done) {
        cudaFuncSetAttribute(hw_kernel, cudaFuncAttributeMaxDynamicSharedMemorySize, hw_smem);
        attr_done = 1;
    }

    const int n4 = NN * NH / 4;

    init_kernel<<<1600, 256>>>(out, out_size);

    // ALL per-layer tables in one latency wave
    const int tot_warps = RWROWS + TWROWS + NL * RQROWS;   // 25350
    tables_all_kernel<<<(tot_warps * 32 + 255) / 256, 256>>>(
        rela, te, Wp, Wn, Wf, W1, W2, qr);

    // counting sort by src (two-phase wide scan)
    hist_kernel<<<(NE + 255) / 256, 256>>>(si);
    sum_chunk_kernel<<<NCHUNK, 256>>>();
    offscan_kernel<<<NCHUNK, 256>>>();
    scatter_sort_kernel<<<(NE + 255) / 256, 256>>>(si, di, ri, rt, bt);

    for (int layer = 0; layer < NL; ++layer) {
        const float* W1L = W1 + layer * 5 * 192;
        const float* W2L = W2 + layer * 5;
        if (layer > 0) {
            hw_kernel<<<dim3((NN + 127) / 128, 3), 256, hw_smem>>>(Wp, Wn, Wf, W1L);
            zero_next_kernel<<<(n4 + 255) / 256, 256>>>();
            score_kernel<<<(NE / 2 + 255) / 256, 256>>>(W2L, layer);
        }
        edge_kernel<<<1184, 256>>>(layer);
    }

    out_kernel<<<(NN * 32 + 255) / 256, 256>>>(Wc, bc, ob, oe, out);
}

// round 16
// speedup vs baseline: 1.2824x; 1.0202x over previous
#include <cuda_runtime.h>
#include <cuda_fp16.h>

#define NB 32
#define NN 100000
#define NE 1000000
#define NH 64
#define NL 3
#define NRELP 231
#define NTA 365
#define NENT 7128
#define FULLM 0xffffffffu
#define CH 1024
#define NCHUNK 98   // ceil(NN/CH)
#define RWROWS (NL * 3 * NRELP)     // 2079
#define TWROWS (3 * NTA)            // 1095
#define RQROWS (NB * NRELP)         // 7392

typedef unsigned long long ull;

// ---------------- device scratch ----------------
static __device__ float   g_next[NN * NH];                       // 25.6 MB (pre-relu aggregate)
static __device__ __align__(16) __half2 g_hWh[3 * NN * 32];      // 38.4 MB transformed hidden (fp16)
static __device__ __align__(16) __half2 g_RWh[RWROWS * 32];      // [layer][cls][rel] rela @ W^T (fp16)
static __device__ __align__(16) __half2 g_TWh[TWROWS * 32];      // [cls][ta] time @ W^T (fp16)
static __device__ __align__(16) int2 g_eMeta[NE];   // {src|cls<<17|ta<<19, dst|rel<<17|b<<25}
static __device__ __align__(8) float g_score[NE];
static __device__ float   g_score0[RQROWS];         // layer-0 score table (hidden=0)
static __device__ float   g_hv[NN * 8];
static __device__ float   g_rq[NL * RQROWS * 8];    // [layer][b*NRELP+rel][8]
static __device__ int     g_hist[NN];
static __device__ int     g_off[NN];
static __device__ int     g_part[NCHUNK];

#define FMA2(d, a, b, c) \
    asm("fma.rn.f32x2 %0, %1, %2, %3;" : "=l"(d) : "l"(a), "l"(b), "l"(c))

__device__ __forceinline__ ull dup_f(float x) {
    ull r; unsigned u = __float_as_uint(x);
    asm("mov.b64 %0, {%1, %1};" : "=l"(r) : "r"(u));
    return r;
}
__device__ __forceinline__ void red4(float* p, float x, float y, float z, float w) {
    asm volatile("red.global.add.v4.f32 [%0], {%1, %2, %3, %4};"
                 :: "l"(p), "f"(x), "f"(y), "f"(z), "f"(w) : "memory");
}

// ---------------- fused init: g_next, g_hist, out ----------------
__global__ void init_kernel(float* out, int n_out) {
    int i = blockIdx.x * blockDim.x + threadIdx.x;
    int stride = gridDim.x * blockDim.x;
    const int n4 = NN * NH / 4;
    for (int j = i; j < n4; j += stride)
        ((float4*)g_next)[j] = make_float4(0.f, 0.f, 0.f, 0.f);
    for (int j = i; j < n_out; j += stride) out[j] = 0.f;
}

// hist zero moved to sort stream (it feeds hist_kernel there)
__global__ void hist_zero_kernel() {
    int i = blockIdx.x * blockDim.x + threadIdx.x;
    if (i < NN) g_hist[i] = 0;
}

// ---------------- zero g_next (between layers, after hw consumed it) ----------------
__global__ void zero_next_kernel() {
    int i = blockIdx.x * blockDim.x + threadIdx.x;
    const int n4 = NN * NH / 4;
    if (i < n4) ((float4*)g_next)[i] = make_float4(0.f, 0.f, 0.f, 0.f);
}

// ---------------- counting sort by src ----------------
__global__ void hist_kernel(const int* __restrict__ src_idx) {
    int e = blockIdx.x * blockDim.x + threadIdx.x;
    if (e < NE) atomicAdd(&g_hist[src_idx[e]], 1);
}
// phase 1: per-chunk sums (98 blocks, 4 loads/thread)
__global__ void sum_chunk_kernel() {
    __shared__ int sd[256];
    int b = blockIdx.x, t = threadIdx.x;
    int idx = b * CH + t * 4;
    int s = 0;
    if (idx + 0 < NN) s += g_hist[idx + 0];
    if (idx + 1 < NN) s += g_hist[idx + 1];
    if (idx + 2 < NN) s += g_hist[idx + 2];
    if (idx + 3 < NN) s += g_hist[idx + 3];
    sd[t] = s; __syncthreads();
    for (int o = 128; o; o >>= 1) { if (t < o) sd[t] += sd[t + o]; __syncthreads(); }
    if (t == 0) g_part[b] = sd[0];
}
// phase 2: prefix over 98 chunk partials (warp-cheap) + in-chunk scan
__global__ void offscan_kernel() {
    __shared__ int sd[256];
    __shared__ int sbase;
    int b = blockIdx.x, t = threadIdx.x;
    if (t < 32) {
        int s = 0;
        for (int i = t; i < b; i += 32) s += g_part[i];
#pragma unroll
        for (int o = 16; o; o >>= 1) s += __shfl_xor_sync(FULLM, s, o);
        if (t == 0) sbase = s;
    }
    __syncthreads();
    int chunkbase = sbase;
    int idx = b * CH + t * 4;
    int h0 = (idx + 0 < NN) ? g_hist[idx + 0] : 0;
    int h1 = (idx + 1 < NN) ? g_hist[idx + 1] : 0;
    int h2 = (idx + 2 < NN) ? g_hist[idx + 2] : 0;
    int h3 = (idx + 3 < NN) ? g_hist[idx + 3] : 0;
    int sum = h0 + h1 + h2 + h3;
    sd[t] = sum; __syncthreads();
    for (int o = 1; o < 256; o <<= 1) {
        int v = (t >= o) ? sd[t - o] : 0;
        __syncthreads();
        sd[t] += v;
        __syncthreads();
    }
    int base = chunkbase + sd[t] - sum;
    if (idx + 0 < NN) g_off[idx + 0] = base;
    if (idx + 1 < NN) g_off[idx + 1] = base + h0;
    if (idx + 2 < NN) g_off[idx + 2] = base + h0 + h1;
    if (idx + 3 < NN) g_off[idx + 3] = base + h0 + h1 + h2;
}
__global__ void scatter_sort_kernel(const int* __restrict__ src_idx,
                                    const int* __restrict__ dst_idx,
                                    const int* __restrict__ rel_idx,
                                    const int* __restrict__ rel_time,
                                    const int* __restrict__ batch_idx) {
    int e = blockIdx.x * blockDim.x + threadIdx.x;
    if (e >= NE) return;
    int src = src_idx[e];
    int rt  = rel_time[e];
    int cls = rt > 0 ? 2 : (rt == 0 ? 1 : 0);  // 0=past(Wp) 1=now(Wn) 2=future(Wf)
    int ta  = rt < 0 ? -rt : rt;
    int rel = rel_idx[e];
    int pos = atomicAdd(&g_off[src], 1);
    g_eMeta[pos] = make_int2(src | (cls << 17) | (ta << 19),
                             dst_idx[e] | (rel << 17) | (batch_idx[e] << 25));
}

// ---------------- ALL per-layer tables in one launch ----------------
__global__ void tables_all_kernel(const float* __restrict__ rela,
                                  const float* __restrict__ timeE,
                                  const float* __restrict__ Wp,
                                  const float* __restrict__ Wn,
                                  const float* __restrict__ Wf,
                                  const float* __restrict__ W1,
                                  const float* __restrict__ W2,
                                  const int* __restrict__ query_rel) {
    int w = (blockIdx.x * blockDim.x + threadIdx.x) >> 5;
    int lane = threadIdx.x & 31;
    if (w < RWROWS + TWROWS) {
        const float* in; __half2* out; int cls;
        if (w < RWROWS) {
            int layer = w / (3 * NRELP);
            int r2 = w % (3 * NRELP);
            cls = r2 / NRELP;
            in = rela + (layer * NRELP + (r2 % NRELP)) * NH;
            out = g_RWh + w * 32;
        } else {
            int w2 = w - RWROWS;
            cls = w2 / NTA;
            in = timeE + (w2 % NTA) * NH;
            out = g_TWh + w2 * 32;
        }
        const float* W = (cls == 0) ? Wp : ((cls == 1) ? Wn : Wf);
        float2 ev = __ldg((const float2*)&in[2 * lane]);
        int h0 = 2 * lane;
        float a0 = 0.f, a1 = 0.f;
#pragma unroll 8
        for (int k2 = 0; k2 < 32; ++k2) {
            float bx = __shfl_sync(FULLM, ev.x, k2);
            float by = __shfl_sync(FULLM, ev.y, k2);
            float2 w0 = __ldg((const float2*)&W[h0 * 64 + 2 * k2]);
            float2 w1 = __ldg((const float2*)&W[(h0 + 1) * 64 + 2 * k2]);
            a0 += bx * w0.x + by * w0.y;
            a1 += bx * w1.x + by * w1.y;
        }
        out[lane] = __floats2half2_rn(a0, a1);
        return;
    }
    int wq = w - (RWROWS + TWROWS);
    if (wq >= NL * RQROWS) return;
    int layer = wq / RQROWS;
    int rr = wq % RQROWS;
    int b = rr / NRELP, r = rr % NRELP;
    const float* relaL = rela + layer * NRELP * NH;
    const float* W1L = W1 + layer * 5 * 192;
    int qrb = __ldg(&query_rel[b]);
    float2 re = __ldg((const float2*)&relaL[r * 64 + 2 * lane]);
    float2 qe = __ldg((const float2*)&relaL[qrb * 64 + 2 * lane]);
    float p[5];
#pragma unroll
    for (int a = 0; a < 5; ++a) {
        float2 v  = __ldg((const float2*)&W1L[a * 192 + 64 + 2 * lane]);
        float2 ww = __ldg((const float2*)&W1L[a * 192 + 128 + 2 * lane]);
        p[a] = re.x * v.x + re.y * v.y + qe.x * ww.x + qe.y * ww.y;
    }
#pragma unroll
    for (int a = 0; a < 5; ++a)
#pragma unroll
        for (int off = 16; off; off >>= 1) p[a] += __shfl_xor_sync(FULLM, p[a], off);
    if (lane == 0) {
#pragma unroll
        for (int a = 0; a < 5; ++a) g_rq[wq * 8 + a] = p[a];
        if (layer == 0) {
            float z = 0.f;
#pragma unroll
            for (int a = 0; a < 5; ++a) z += fmaxf(p[a], 0.f) * __ldg(&W2[a]);
            g_score0[rr] = 1.f / (1.f + __expf(-z));
        }
    }
}

// hW[cls][node] = relu(g_next)[node] @ W_cls^T -> fp16; cls==0 blocks also emit hv
__global__ void __launch_bounds__(256) hw_kernel(const float* __restrict__ Wp,
                                                 const float* __restrict__ Wn,
                                                 const float* __restrict__ Wf,
                                                 const float* __restrict__ W1L) {
    extern __shared__ float dyn[];
    float* sW = dyn;            // 4352 floats
    float* sT = dyn + 4352;     // 128*66 floats
    float* sU = dyn + 4352 + 128 * 66;  // 5*64 floats
    int cls = blockIdx.y;
    const float* W = (cls == 0) ? Wp : ((cls == 1) ? Wn : Wf);
    int t = threadIdx.x;
    for (int idx = t; idx < 4096; idx += 256) {
        int h = idx >> 6, k = idx & 63;
        sW[k * 68 + h + (h >= 32 ? 4 : 0)] = __ldg(&W[h * 64 + k]);
    }
    if (cls == 0) {
        for (int idx = t; idx < 5 * 64; idx += 256) {
            int a = idx >> 6, k = idx & 63;
            sU[idx] = __ldg(&W1L[a * 192 + k]);
        }
    }
    __syncthreads();
    for (int tile = blockIdx.x * 128; tile < NN; tile += gridDim.x * 128) {
        int nN = min(128, NN - tile);
        for (int j = t; j < nN * 32; j += 256) {
            int nl = j >> 5, l = j & 31;
            float2 v = *(const float2*)&g_next[(size_t)(tile + nl) * 64 + 2 * l];
            v.x = fmaxf(v.x, 0.f); v.y = fmaxf(v.y, 0.f);   // relu inline
            *(float2*)&sT[nl * 66 + 2 * l] = v;
        }
        __syncthreads();
        int slot = t >> 1, p = t & 1;
        if (slot < nN) {
            if (cls == 0) {
                const float* row = sT + slot * 66 + p * 32;
                float pa[5] = {0.f, 0.f, 0.f, 0.f, 0.f};
#pragma unroll 8
                for (int k = 0; k < 32; ++k) {
                    float hk = row[k];
#pragma unroll
                    for (int a = 0; a < 5; ++a) pa[a] += hk * sU[a * 64 + p * 32 + k];
                }
#pragma unroll
                for (int a = 0; a < 5; ++a) pa[a] += __shfl_xor_sync(FULLM, pa[a], 1);
                if (p == 0) {
                    float* hvp = g_hv + (size_t)(tile + slot) * 8;
                    *(float4*)hvp = make_float4(pa[0], pa[1], pa[2], pa[3]);
                    hvp[4] = pa[4];
                }
            }
            const float* wb = sW + p * 36;
            const float* er = sT + slot * 66;
            ull acc[16];
#pragma unroll
            for (int j = 0; j < 16; ++j) acc[j] = 0ull;
#pragma unroll 4
            for (int k2 = 0; k2 < 32; ++k2) {
                float2 e2 = *(const float2*)&er[2 * k2];
                ull b0 = dup_f(e2.x);
                ull b1 = dup_f(e2.y);
                const float* r0 = wb + (2 * k2) * 68;
                const float* r1 = r0 + 68;
#pragma unroll
                for (int j = 0; j < 8; ++j) {
                    ulonglong2 w0 = *(const ulonglong2*)(r0 + 4 * j);
                    FMA2(acc[2 * j],     w0.x, b0, acc[2 * j]);
                    FMA2(acc[2 * j + 1], w0.y, b0, acc[2 * j + 1]);
                }
#pragma unroll
                for (int j = 0; j < 8; ++j) {
                    ulonglong2 w1 = *(const ulonglong2*)(r1 + 4 * j);
                    FMA2(acc[2 * j],     w1.x, b1, acc[2 * j]);
                    FMA2(acc[2 * j + 1], w1.y, b1, acc[2 * j + 1]);
                }
            }
            __half2 hh[16];
#pragma unroll
            for (int j = 0; j < 16; ++j) {
                float2 f = *(float2*)&acc[j];
                hh[j] = __float22half2_rn(f);
            }
            __half2* ob = g_hWh + ((size_t)cls * NN + tile + slot) * 32 + p * 16;
#pragma unroll
            for (int j = 0; j < 4; ++j)
                *(uint4*)(ob + 4 * j) = *(uint4*)(hh + 4 * j);
        }
        __syncthreads();
    }
}

// ---------------- per-edge score (layers > 0), 2 edges per thread ----------------
__global__ void score_kernel(const float* __restrict__ W2L, int layer) {
    int i = blockIdx.x * blockDim.x + threadIdx.x;
    int e0 = 2 * i;
    if (e0 >= NE) return;
    const float* rqL = g_rq + (size_t)layer * RQROWS * 8;
    int4 mm = __ldg((const int4*)&g_eMeta[e0]);   // two int2 metas
    float w20 = __ldg(&W2L[0]), w21 = __ldg(&W2L[1]), w22 = __ldg(&W2L[2]);
    float w23 = __ldg(&W2L[3]), w24 = __ldg(&W2L[4]);
    float sc[2];
#pragma unroll
    for (int k = 0; k < 2; ++k) {
        int mx = k ? mm.z : mm.x;
        int my = k ? mm.w : mm.y;
        int src = mx & 0x1FFFF;
        int rel = (my >> 17) & 0xFF;
        int b   = (my >> 25) & 0x1F;
        const float4* rq4 = (const float4*)&rqL[(b * NRELP + rel) * 8];
        float4 r0 = __ldg(&rq4[0]); float4 r1 = __ldg(&rq4[1]);
        const float4* hv4 = (const float4*)&g_hv[src * 8];
        float4 h0 = __ldg(&hv4[0]); float4 h1 = __ldg(&hv4[1]);
        float z = fmaxf(r0.x + h0.x, 0.f) * w20 + fmaxf(r0.y + h0.y, 0.f) * w21
                + fmaxf(r0.z + h0.z, 0.f) * w22 + fmaxf(r0.w + h0.w, 0.f) * w23
                + fmaxf(r1.x + h1.x, 0.f) * w24;
        sc[k] = 1.f / (1.f + __expf(-z));
    }
    *(float2*)&g_score[e0] = make_float2(sc[0], sc[1]);
}

// ---------------- main edge kernel (half-warp per edge, fp16 tables) ----------------
__global__ void __launch_bounds__(256) edge_kernel(int layer) {
    int gw = (blockIdx.x * blockDim.x + threadIdx.x) >> 5;
    int lane = threadIdx.x & 31;
    int half = lane >> 4;
    int hl = lane & 15;
    int nw = (gridDim.x * blockDim.x) >> 5;
    const __half2* RWl = g_RWh + (size_t)layer * (3 * NRELP) * 32;
    int isL0 = (layer == 0);
    for (int base = gw * 8; base < NE; base += nw * 8) {
#pragma unroll
        for (int p = 0; p < 4; ++p) {
            int e = base + 2 * p + half;
            int2 m = __ldg(&g_eMeta[e]);
            int src = m.x & 0x1FFFF;
            int cls = (m.x >> 17) & 3;
            int ta  = (m.x >> 19) & 0x1FF;
            int dst = m.y & 0x1FFFF;
            int rel = (m.y >> 17) & 0xFF;
            float s;
            if (isL0) {
                int b = (m.y >> 25) & 0x1F;
                s = __ldg(&g_score0[b * NRELP + rel]);
            } else {
                s = __ldg(&g_score[e]);
            }
            uint2 ra = __ldg((const uint2*)(RWl + (cls * NRELP + rel) * 32 + 2 * hl));
            uint2 tb = __ldg((const uint2*)(g_TWh + (cls * NTA + ta) * 32 + 2 * hl));
            __half2 t0 = __hadd2(*(__half2*)&ra.x, *(__half2*)&tb.x);
            __half2 t1 = __hadd2(*(__half2*)&ra.y, *(__half2*)&tb.y);
            if (!isL0) {
                uint2 hw = __ldg((const uint2*)(g_hWh + ((size_t)cls * NN + src) * 32 + 2 * hl));
                t0 = __hadd2(t0, *(__half2*)&hw.x);
                t1 = __hadd2(t1, *(__half2*)&hw.y);
            }
            float2 f01 = __half22float2(t0);
            float2 f23 = __half22float2(t1);
            red4(&g_next[(size_t)dst * 64 + 4 * hl], s * f01.x, s * f01.y, s * f23.x, s * f23.y);
        }
    }
}

// ---------------- output: relu(g_next).Wc + bc ----------------
__global__ void out_kernel(const float* __restrict__ Wc, const float* __restrict__ bc,
                           const int* __restrict__ ob, const int* __restrict__ oe,
                           float* __restrict__ out) {
    int gw = (blockIdx.x * blockDim.x + threadIdx.x) >> 5;
    int lane = threadIdx.x & 31;
    if (gw >= NN) return;
    float2 h = *(const float2*)&g_next[(size_t)gw * 64 + 2 * lane];
    h.x = fmaxf(h.x, 0.f); h.y = fmaxf(h.y, 0.f);
    float2 w = __ldg((const float2*)&Wc[2 * lane]);
    float p = h.x * w.x + h.y * w.y;
#pragma unroll
    for (int off = 16; off; off >>= 1) p += __shfl_xor_sync(FULLM, p, off);
    if (lane == 0) out[ob[gw] * NENT + oe[gw]] = p + bc[0];
}

// ---------------- host launch ----------------
extern "C" void kernel_launch(void* const* d_in, const int* in_sizes, int n_in,
                              void* d_out, int out_size) {
    const int *bt, *si, *di, *ri, *rt, *qr, *ob, *oe;
    const float *rela, *te, *Wp, *Wn, *Wf, *W1, *W2, *Wc, *bc;

    if (in_sizes[0] == NE) {
        bt = (const int*)d_in[0];  si = (const int*)d_in[1];
        di = (const int*)d_in[2];  ri = (const int*)d_in[3];
        rt = (const int*)d_in[4];  qr = (const int*)d_in[5];
        ob = (const int*)d_in[6];  oe = (const int*)d_in[7];
        rela = (const float*)d_in[8];  te = (const float*)d_in[9];
        Wp = (const float*)d_in[10]; Wn = (const float*)d_in[11];
        Wf = (const float*)d_in[12]; W1 = (const float*)d_in[13];
        W2 = (const float*)d_in[14]; Wc = (const float*)d_in[15];
        bc = (const float*)d_in[16];
    } else {
        rela = (const float*)d_in[0];  te = (const float*)d_in[1];
        Wp = (const float*)d_in[2]; Wn = (const float*)d_in[3];
        Wf = (const float*)d_in[4]; W1 = (const float*)d_in[5];
        W2 = (const float*)d_in[6]; Wc = (const float*)d_in[7];
        bc = (const float*)d_in[8];
        bt = (const int*)d_in[9];  si = (const int*)d_in[10];
        di = (const int*)d_in[11]; ri = (const int*)d_in[12];
        rt = (const int*)d_in[13]; qr = (const int*)d_in[14];
        ob = (const int*)d_in[15]; oe = (const int*)d_in[16];
    }

    float* out = (float*)d_out;

    static int init_done = 0;
    static cudaStream_t s1;
    static cudaEvent_t evFork, evSort, evH, evZ;
    const int hw_smem = (4352 + 128 * 66 + 5 * 64) * 4;   // 52480 B
    if (!init_done) {
        cudaFuncSetAttribute(hw_kernel, cudaFuncAttributeMaxDynamicSharedMemorySize, hw_smem);
        cudaStreamCreateWithFlags(&s1, cudaStreamNonBlocking);
        cudaEventCreateWithFlags(&evFork, cudaEventDisableTiming);
        cudaEventCreateWithFlags(&evSort, cudaEventDisableTiming);
        cudaEventCreateWithFlags(&evH, cudaEventDisableTiming);
        cudaEventCreateWithFlags(&evZ, cudaEventDisableTiming);
        init_done = 1;
    }

    const int n4 = NN * NH / 4;
    const int tot_warps = RWROWS + TWROWS + NL * RQROWS;   // 25350

    // ---- front fork: sort chain (s1) || init + tables (s0) ----
    cudaEventRecord(evFork, 0);
    cudaStreamWaitEvent(s1, evFork, 0);
    hist_zero_kernel<<<(NN + 255) / 256, 256, 0, s1>>>();
    hist_kernel<<<(NE + 255) / 256, 256, 0, s1>>>(si);
    sum_chunk_kernel<<<NCHUNK, 256, 0, s1>>>();
    offscan_kernel<<<NCHUNK, 256, 0, s1>>>();
    scatter_sort_kernel<<<(NE + 255) / 256, 256, 0, s1>>>(si, di, ri, rt, bt);
    cudaEventRecord(evSort, s1);

    init_kernel<<<1600, 256>>>(out, out_size);
    tables_all_kernel<<<(tot_warps * 32 + 255) / 256, 256>>>(
        rela, te, Wp, Wn, Wf, W1, W2, qr);
    cudaStreamWaitEvent(0, evSort, 0);

    for (int layer = 0; layer < NL; ++layer) {
        const float* W1L = W1 + layer * 5 * 192;
        const float* W2L = W2 + layer * 5;
        if (layer > 0) {
            hw_kernel<<<dim3((NN + 127) / 128, 3), 256, hw_smem>>>(Wp, Wn, Wf, W1L);
            // fork: zero_next (s1) || score (s0); edge waits for both
            cudaEventRecord(evH, 0);
            cudaStreamWaitEvent(s1, evH, 0);
            zero_next_kernel<<<(n4 + 255) / 256, 256, 0, s1>>>();
            cudaEventRecord(evZ, s1);
            score_kernel<<<(NE / 2 + 255) / 256, 256>>>(W2L, layer);
            cudaStreamWaitEvent(0, evZ, 0);
        }
        edge_kernel<<<1184, 256>>>(layer);
    }

    out_kernel<<<(NN * 32 + 255) / 256, 256>>>(Wc, bc, ob, oe, out);
}